// round 1
// baseline (speedup 1.0000x reference)
#include <cuda_runtime.h>
#include <math.h>

#define B_ 64
#define S_ 512
#define E_ 512
#define H_ 8
#define D_ 64
#define L_ 4
#define O_ 1000
#define KW_ 5
#define STRIDE_ 5
#define LOUT_ 102
#define BH_ (B_*H_)
#define M_ (B_*S_)   /* 32768 */

// ---------------- scratch (device globals: no allocation allowed) ------------
__device__ float g_out[M_*E_];            // activations [B,S,E]
__device__ float g_q[BH_*S_*D_];
__device__ float g_k[BH_*S_*D_];
__device__ float g_v[BH_*S_*D_];
__device__ float g_sc[(size_t)BH_*S_*S_]; // attention scores [B*H,S,S]
__device__ float g_cat[M_*E_];            // heads in [B,S,H*D] layout
__device__ float g_mh[M_*E_];
__device__ float g_ff[M_*2*E_];
__device__ float g_pooled[B_*LOUT_];

// ---------------- embedding gather + mask ------------------------------------
__global__ void embed_kernel(const int* __restrict__ tokens,
                             const float* __restrict__ emb) {
    int idx = blockIdx.x * 256 + threadIdx.x;       // over M_*E_
    int e = idx & (E_ - 1);
    int m = idx >> 9;                               // /E_ (512)
    int t = tokens[m];
    g_out[idx] = (t > 0) ? emb[t * E_ + e] : 0.0f;  // mask = sign(token)
}

// ---------------- QKV projection: out[B*S,E] @ W[h][E,D] -> [B,H,S,D] --------
__global__ void qkv_kernel(const float* __restrict__ Wq, const float* __restrict__ bq,
                           const float* __restrict__ Wk, const float* __restrict__ bk,
                           const float* __restrict__ Wv, const float* __restrict__ bv) {
    // grid: (M_/64, H_, 3)  block: (16,16)
    const float* W; const float* bias; float* dst;
    if (blockIdx.z == 0)      { W = Wq; bias = bq; dst = g_q; }
    else if (blockIdx.z == 1) { W = Wk; bias = bk; dst = g_k; }
    else                      { W = Wv; bias = bv; dst = g_v; }
    int h  = blockIdx.y;
    int m0 = blockIdx.x * 64;
    const float* Wh = W + h * (E_ * D_);

    __shared__ float As[16][65];
    __shared__ float Bs[16][64];
    int tx = threadIdx.x, ty = threadIdx.y;
    int t  = ty * 16 + tx;
    float acc[4][4] = {};

    for (int k0 = 0; k0 < E_; k0 += 16) {
        #pragma unroll
        for (int l = 0; l < 4; l++) {
            int e = t + 256 * l;
            int m = e >> 4, k = e & 15;
            As[k][m] = g_out[(m0 + m) * E_ + k0 + k];
        }
        #pragma unroll
        for (int l = 0; l < 4; l++) {
            int e = t + 256 * l;
            int k = e >> 6, n = e & 63;
            Bs[k][n] = Wh[(k0 + k) * D_ + n];
        }
        __syncthreads();
        #pragma unroll
        for (int kk = 0; kk < 16; kk++) {
            float a[4], b[4];
            #pragma unroll
            for (int i = 0; i < 4; i++) a[i] = As[kk][ty + i * 16];
            #pragma unroll
            for (int j = 0; j < 4; j++) b[j] = Bs[kk][tx + j * 16];
            #pragma unroll
            for (int i = 0; i < 4; i++)
                #pragma unroll
                for (int j = 0; j < 4; j++)
                    acc[i][j] += a[i] * b[j];
        }
        __syncthreads();
    }
    #pragma unroll
    for (int i = 0; i < 4; i++) {
        int m = m0 + ty + i * 16;
        int b = m >> 9;          // /S_
        int s = m & 511;
        #pragma unroll
        for (int j = 0; j < 4; j++) {
            int d = tx + j * 16;
            dst[((size_t)(b * H_ + h) * S_ + s) * D_ + d] = acc[i][j] + bias[h * D_ + d];
        }
    }
}

// ---------------- scores: q @ k^T * scale  (batched, K=64) -------------------
__global__ void scores_kernel(float scale) {
    // grid: (8 t-tiles, 8 s-tiles, BH_)  block (16,16)
    int bh = blockIdx.z;
    int s0 = blockIdx.y * 64, t0 = blockIdx.x * 64;
    const float* q = g_q + (size_t)bh * S_ * D_;
    const float* k = g_k + (size_t)bh * S_ * D_;

    __shared__ float Qs[64][65], Ks[64][65];
    int tx = threadIdx.x, ty = threadIdx.y;
    int t  = ty * 16 + tx;
    #pragma unroll
    for (int l = 0; l < 16; l++) {
        int e = t + 256 * l;
        int r = e >> 6, c = e & 63;
        Qs[r][c] = q[(s0 + r) * D_ + c];
        Ks[r][c] = k[(t0 + r) * D_ + c];
    }
    __syncthreads();

    float acc[4][4] = {};
    #pragma unroll 8
    for (int kk = 0; kk < 64; kk++) {
        float a[4], b[4];
        #pragma unroll
        for (int i = 0; i < 4; i++) a[i] = Qs[ty + i * 16][kk];
        #pragma unroll
        for (int j = 0; j < 4; j++) b[j] = Ks[tx + j * 16][kk];
        #pragma unroll
        for (int i = 0; i < 4; i++)
            #pragma unroll
            for (int j = 0; j < 4; j++)
                acc[i][j] += a[i] * b[j];
    }
    float* dst = g_sc + (size_t)bh * S_ * S_;
    #pragma unroll
    for (int i = 0; i < 4; i++)
        #pragma unroll
        for (int j = 0; j < 4; j++)
            dst[(s0 + ty + i * 16) * S_ + t0 + tx + j * 16] = acc[i][j] * scale;
}

// ---------------- row softmax over 512 --------------------------------------
__global__ void softmax512_kernel() {
    size_t row = blockIdx.x;
    float* p = g_sc + row * S_;
    int t = threadIdx.x;
    float v0 = p[t], v1 = p[t + 256];

    __shared__ float red[256];
    red[t] = fmaxf(v0, v1);
    __syncthreads();
    for (int s = 128; s > 0; s >>= 1) {
        if (t < s) red[t] = fmaxf(red[t], red[t + s]);
        __syncthreads();
    }
    float mx = red[0];
    __syncthreads();
    float e0 = expf(v0 - mx), e1 = expf(v1 - mx);
    red[t] = e0 + e1;
    __syncthreads();
    for (int s = 128; s > 0; s >>= 1) {
        if (t < s) red[t] += red[t + s];
        __syncthreads();
    }
    float inv = 1.0f / red[0];
    p[t] = e0 * inv;
    p[t + 256] = e1 * inv;
}

// ---------------- attn @ v  ->  cat [B,S,H*D] --------------------------------
__global__ void attnv_kernel() {
    // grid: (S_/64, BH_)  block (16,16)
    int bh = blockIdx.y;
    int s0 = blockIdx.x * 64;
    const float* attn = g_sc + (size_t)bh * S_ * S_;
    const float* v    = g_v  + (size_t)bh * S_ * D_;

    __shared__ float As[16][65];   // [k][s]
    __shared__ float Bs[16][64];   // [k][d]
    int tx = threadIdx.x, ty = threadIdx.y;
    int t  = ty * 16 + tx;
    float acc[4][4] = {};

    for (int k0 = 0; k0 < S_; k0 += 16) {
        #pragma unroll
        for (int l = 0; l < 4; l++) {
            int e = t + 256 * l;
            int m = e >> 4, k = e & 15;
            As[k][m] = attn[(s0 + m) * S_ + k0 + k];
        }
        #pragma unroll
        for (int l = 0; l < 4; l++) {
            int e = t + 256 * l;
            int k = e >> 6, n = e & 63;
            Bs[k][n] = v[(k0 + k) * D_ + n];
        }
        __syncthreads();
        #pragma unroll
        for (int kk = 0; kk < 16; kk++) {
            float a[4], b[4];
            #pragma unroll
            for (int i = 0; i < 4; i++) a[i] = As[kk][ty + i * 16];
            #pragma unroll
            for (int j = 0; j < 4; j++) b[j] = Bs[kk][tx + j * 16];
            #pragma unroll
            for (int i = 0; i < 4; i++)
                #pragma unroll
                for (int j = 0; j < 4; j++)
                    acc[i][j] += a[i] * b[j];
        }
        __syncthreads();
    }
    int b = bh >> 3, h = bh & 7;
    #pragma unroll
    for (int i = 0; i < 4; i++) {
        int s = s0 + ty + i * 16;
        #pragma unroll
        for (int j = 0; j < 4; j++) {
            int d = tx + j * 16;
            g_cat[((size_t)(b * S_ + s)) * E_ + h * D_ + d] = acc[i][j];
        }
    }
}

// ---------------- generic GEMM: C = act(A@B + bias) [+ resid] ---------------
template<int RELU, int RESID>
__global__ void gemm_kernel(const float* __restrict__ A, const float* __restrict__ Bm,
                            const float* __restrict__ bias, const float* __restrict__ resid,
                            float* __restrict__ C, int M, int N, int K) {
    // grid: (N/64, M/64)  block (16,16)
    int n0 = blockIdx.x * 64, m0 = blockIdx.y * 64;
    __shared__ float As[16][65];
    __shared__ float Bs[16][64];
    int tx = threadIdx.x, ty = threadIdx.y;
    int t  = ty * 16 + tx;
    float acc[4][4] = {};

    for (int k0 = 0; k0 < K; k0 += 16) {
        #pragma unroll
        for (int l = 0; l < 4; l++) {
            int e = t + 256 * l;
            int m = e >> 4, k = e & 15;
            As[k][m] = A[(size_t)(m0 + m) * K + k0 + k];
        }
        #pragma unroll
        for (int l = 0; l < 4; l++) {
            int e = t + 256 * l;
            int k = e >> 6, n = e & 63;
            Bs[k][n] = Bm[(size_t)(k0 + k) * N + n0 + n];
        }
        __syncthreads();
        #pragma unroll
        for (int kk = 0; kk < 16; kk++) {
            float a[4], b[4];
            #pragma unroll
            for (int i = 0; i < 4; i++) a[i] = As[kk][ty + i * 16];
            #pragma unroll
            for (int j = 0; j < 4; j++) b[j] = Bs[kk][tx + j * 16];
            #pragma unroll
            for (int i = 0; i < 4; i++)
                #pragma unroll
                for (int j = 0; j < 4; j++)
                    acc[i][j] += a[i] * b[j];
        }
        __syncthreads();
    }
    #pragma unroll
    for (int i = 0; i < 4; i++) {
        int m = m0 + ty + i * 16;
        #pragma unroll
        for (int j = 0; j < 4; j++) {
            int n = n0 + tx + j * 16;
            float r = acc[i][j] + bias[n];
            if (RELU)  r = fmaxf(r, 0.0f);
            if (RESID) r += resid[(size_t)m * N + n];
            C[(size_t)m * N + n] = r;
        }
    }
}

// ---------------- residual add + l2 normalize (rows of 512) ------------------
__global__ void addnorm_kernel() {
    int row = blockIdx.x;
    float* o = g_out + (size_t)row * E_;
    const float* mh = g_mh + (size_t)row * E_;
    int t = threadIdx.x;
    float x0 = o[t] + mh[t];
    float x1 = o[t + 256] + mh[t + 256];
    __shared__ float red[256];
    red[t] = x0 * x0 + x1 * x1;
    __syncthreads();
    for (int s = 128; s > 0; s >>= 1) {
        if (t < s) red[t] += red[t + s];
        __syncthreads();
    }
    float inv = rsqrtf(fmaxf(red[0], 1e-12f));
    o[t]       = x0 * inv;
    o[t + 256] = x1 * inv;
}

// ---------------- conv1d(KW=5, stride=5) pooled ------------------------------
__global__ void conv_kernel(const float* __restrict__ Wc, const float* __restrict__ bc) {
    int b = blockIdx.x / LOUT_;
    int j = blockIdx.x % LOUT_;
    const float* base = g_out + ((size_t)b * S_ + j * STRIDE_) * E_;
    float acc = 0.0f;
    for (int i = threadIdx.x; i < KW_ * E_; i += 256)
        acc += base[i] * Wc[i];
    __shared__ float red[256];
    red[threadIdx.x] = acc;
    __syncthreads();
    for (int s = 128; s > 0; s >>= 1) {
        if (threadIdx.x < s) red[threadIdx.x] += red[threadIdx.x + s];
        __syncthreads();
    }
    if (threadIdx.x == 0) g_pooled[b * LOUT_ + j] = red[0] + bc[0];
}

// ---------------- final dense + softmax over 1000 ----------------------------
__global__ void dense_softmax_kernel(const float* __restrict__ Wd,
                                     const float* __restrict__ bd,
                                     float* __restrict__ outp) {
    int b = blockIdx.x;
    __shared__ float p[LOUT_];
    int t = threadIdx.x;
    if (t < LOUT_) p[t] = g_pooled[b * LOUT_ + t];
    __syncthreads();

    float lg[4];
    #pragma unroll
    for (int u = 0; u < 4; u++) {
        int o = t + u * 256;
        float acc = -1e30f;
        if (o < O_) {
            acc = bd[o];
            for (int j = 0; j < LOUT_; j++)
                acc += p[j] * Wd[j * O_ + o];
        }
        lg[u] = acc;
    }
    __shared__ float red[256];
    float m = fmaxf(fmaxf(lg[0], lg[1]), fmaxf(lg[2], lg[3]));
    red[t] = m;
    __syncthreads();
    for (int s = 128; s > 0; s >>= 1) {
        if (t < s) red[t] = fmaxf(red[t], red[t + s]);
        __syncthreads();
    }
    float mx = red[0];
    __syncthreads();
    float e[4], sum = 0.0f;
    #pragma unroll
    for (int u = 0; u < 4; u++) {
        e[u] = expf(lg[u] - mx);   // masked lanes underflow to 0
        sum += e[u];
    }
    red[t] = sum;
    __syncthreads();
    for (int s = 128; s > 0; s >>= 1) {
        if (t < s) red[t] += red[t + s];
        __syncthreads();
    }
    float inv = 1.0f / red[0];
    #pragma unroll
    for (int u = 0; u < 4; u++) {
        int o = t + u * 256;
        if (o < O_) outp[(size_t)b * O_ + o] = e[u] * inv;
    }
}

// ---------------- host launcher ----------------------------------------------
extern "C" void kernel_launch(void* const* d_in, const int* in_sizes, int n_in,
                              void* d_out, int out_size) {
    const int*   tokens = (const int*)  d_in[0];
    const float* emb    = (const float*)d_in[1];
    const float* Wq     = (const float*)d_in[2];
    const float* bq     = (const float*)d_in[3];
    const float* Wk     = (const float*)d_in[4];
    const float* bk     = (const float*)d_in[5];
    const float* Wv     = (const float*)d_in[6];
    const float* bv     = (const float*)d_in[7];
    const float* Wo     = (const float*)d_in[8];
    const float* bo     = (const float*)d_in[9];
    const float* W1     = (const float*)d_in[10];
    const float* b1     = (const float*)d_in[11];
    const float* W2     = (const float*)d_in[12];
    const float* b2     = (const float*)d_in[13];
    const float* Wc     = (const float*)d_in[14];
    const float* bc     = (const float*)d_in[15];
    const float* Wd     = (const float*)d_in[16];
    const float* bd     = (const float*)d_in[17];
    float* outp = (float*)d_out;
    (void)in_sizes; (void)n_in; (void)out_size;

    float *p_out, *p_cat, *p_mh, *p_ff;
    cudaGetSymbolAddress((void**)&p_out, g_out);
    cudaGetSymbolAddress((void**)&p_cat, g_cat);
    cudaGetSymbolAddress((void**)&p_mh,  g_mh);
    cudaGetSymbolAddress((void**)&p_ff,  g_ff);

    dim3 thr(16, 16);
    const float scale = 0.044194173824159216f;  // 1/sqrt(E=512)

    embed_kernel<<<(M_ * E_) / 256, 256>>>(tokens, emb);

    for (int i = 0; i < L_; i++) {
        qkv_kernel<<<dim3(M_ / 64, H_, 3), thr>>>(
            Wq + (size_t)i * H_ * E_ * D_, bq + (size_t)i * H_ * D_,
            Wk + (size_t)i * H_ * E_ * D_, bk + (size_t)i * H_ * D_,
            Wv + (size_t)i * H_ * E_ * D_, bv + (size_t)i * H_ * D_);

        scores_kernel<<<dim3(8, 8, BH_), thr>>>(scale);
        softmax512_kernel<<<BH_ * S_, 256>>>();
        attnv_kernel<<<dim3(8, BH_), thr>>>();

        // mh = cat @ Wo + bo
        gemm_kernel<0, 0><<<dim3(E_ / 64, M_ / 64), thr>>>(
            p_cat, Wo + (size_t)i * E_ * E_, bo + (size_t)i * E_, nullptr, p_mh,
            M_, E_, E_);

        addnorm_kernel<<<M_, 256>>>();

        // ff = relu(out @ W1 + b1)
        gemm_kernel<1, 0><<<dim3(2 * E_ / 64, M_ / 64), thr>>>(
            p_out, W1 + (size_t)i * E_ * 2 * E_, b1 + (size_t)i * 2 * E_, nullptr, p_ff,
            M_, 2 * E_, E_);

        // out = ff @ W2 + b2 + out
        gemm_kernel<0, 1><<<dim3(E_ / 64, M_ / 64), thr>>>(
            p_ff, W2 + (size_t)i * 2 * E_ * E_, b2 + (size_t)i * E_, p_out, p_out,
            M_, E_, 2 * E_);
    }

    conv_kernel<<<B_ * LOUT_, 256>>>(Wc, bc);
    dense_softmax_kernel<<<B_, 256>>>(Wd, bd, outp);
}

// round 4
// speedup vs baseline: 3.7678x; 3.7678x over previous
#include <cuda_runtime.h>
#include <cstdint>
#include <math.h>

#define B_ 64
#define S_ 512
#define E_ 512
#define H_ 8
#define D_ 64
#define L_ 4
#define O_ 1000
#define KW_ 5
#define STRIDE_ 5
#define LOUT_ 102
#define BH_ (B_*H_)
#define M_ (B_*S_)   /* 32768 */

// ---------------- scratch ----------------------------------------------------
__device__ float g_out[M_*E_];              // activations [B,S,E]
__device__ float g_q[M_*E_];                // [B,S,H*D]
__device__ float g_k[M_*E_];                // [B,S,H*D]
__device__ float g_vt[M_*E_];               // [B,H,D,S]  (pre-transposed V)
__device__ float g_sc[(size_t)BH_*S_*S_];   // [B*H,S,S]
__device__ float g_cat[M_*E_];              // [B,S,H*D]
__device__ float g_mh[M_*E_];
__device__ float g_ff[M_*2*E_];
__device__ float g_pooled[B_*LOUT_];
#define LWT_ 2097152
__device__ float g_wt[(size_t)L_*LWT_];     // transposed weights per layer
#define QT_  0
#define KT_  262144
#define VTW_ 524288
#define OT_  786432
#define W1T_ 1048576
#define W2T_ 1572864

// ---------------- helpers -----------------------------------------------------
__device__ __forceinline__ uint32_t smem_u32(const void* p) {
    uint32_t a;
    asm("{ .reg .u64 t; cvta.to.shared.u64 t, %1; cvt.u32.u64 %0, t; }" : "=r"(a) : "l"(p));
    return a;
}
__device__ __forceinline__ void cp_async16(uint32_t dst, const void* src) {
    asm volatile("cp.async.cg.shared.global [%0], [%1], 16;" :: "r"(dst), "l"(src) : "memory");
}
__device__ __forceinline__ void cp_commit() {
    asm volatile("cp.async.commit_group;" ::: "memory");
}
__device__ __forceinline__ void cp_wait0() {
    asm volatile("cp.async.wait_group 0;" ::: "memory");
}
__device__ __forceinline__ void mma_tf32(float* c, const uint32_t* a, const uint32_t* b) {
    asm volatile(
        "mma.sync.aligned.m16n8k8.row.col.f32.tf32.tf32.f32 "
        "{%0,%1,%2,%3}, {%4,%5,%6,%7}, {%8,%9}, {%0,%1,%2,%3};"
        : "+f"(c[0]), "+f"(c[1]), "+f"(c[2]), "+f"(c[3])
        : "r"(a[0]), "r"(a[1]), "r"(a[2]), "r"(a[3]), "r"(b[0]), "r"(b[1]));
}

// smem row stride 36 floats: bank = 4*row + col (mod 32) -> conflict-free frags
#define SPAD 36

// async tile loader: R rows x 32 fp32 cols from src (row stride ld)
template<int R>
__device__ __forceinline__ void load_tile(float* sm, const float* __restrict__ src, int ld) {
    const int t = threadIdx.x;
    #pragma unroll
    for (int i = 0; i < (R * 8) / 256; i++) {
        int idx = t + i * 256;
        int r = idx >> 3, c4 = idx & 7;
        cp_async16(smem_u32(sm + r * SPAD + c4 * 4), src + (size_t)r * ld + c4 * 4);
    }
}

// ---------------- tf32 mma.sync GEMM -----------------------------------------
// MODE: 0=PROJ(bias), 1=VPROJ(bias, transposed C), 2=SCORES(scale, z-batched),
//       3=ATTNV(z-batched), 4=FFN1(bias+relu), 5=FFN2(bias+resid)
struct GArgs {
    const float* A; const float* B; float* C;
    const float* bias; const float* resid;
    int lda, ldb, ldc; float scale;
};

template<int MODE, int NT, int NC>
__global__ __launch_bounds__(256) void gemmT(GArgs g) {
    extern __shared__ float sm[];
    constexpr int NF = NT / 32;               // n-frags per warp (4 or 2)
    constexpr int ASZ = 128 * SPAD;
    constexpr int BSZ = NT * SPAD;
    float* A_sm[2] = { sm, sm + ASZ };
    float* B_sm[2] = { sm + 2 * ASZ, sm + 2 * ASZ + BSZ };

    const int tid = threadIdx.x;
    const int w = tid >> 5, lane = tid & 31;
    const int gq = lane >> 2, q = lane & 3;
    const int wm = (w >> 2) * 64;
    const int wn = (w & 3) * (NT / 4);

    const int z = blockIdx.z;
    const int m0 = blockIdx.y * 128, n0 = blockIdx.x * NT;
    size_t a0 = 0, b0 = 0;
    if (MODE == 2) { a0 = (size_t)(z >> 3) * (S_ * E_) + (size_t)(z & 7) * 64; b0 = a0; }
    if (MODE == 3) { a0 = (size_t)z * (S_ * S_); b0 = (size_t)z * (D_ * S_); }
    const float* Ab = g.A + a0 + (size_t)m0 * g.lda;
    const float* Bb = g.B + b0 + (size_t)n0 * g.ldb;

    float c[4][NF][4];
    #pragma unroll
    for (int mt = 0; mt < 4; mt++)
        #pragma unroll
        for (int nt = 0; nt < NF; nt++)
            #pragma unroll
            for (int j = 0; j < 4; j++) c[mt][nt][j] = 0.0f;

    load_tile<128>(A_sm[0], Ab, g.lda);
    load_tile<NT>(B_sm[0], Bb, g.ldb);
    cp_commit();

    #pragma unroll 1
    for (int ch = 0; ch < NC; ch++) {
        const int cur = ch & 1;
        cp_wait0();
        __syncthreads();
        if (ch + 1 < NC) {
            load_tile<128>(A_sm[cur ^ 1], Ab + (ch + 1) * 32, g.lda);
            load_tile<NT>(B_sm[cur ^ 1], Bb + (ch + 1) * 32, g.ldb);
            cp_commit();
        }
        const float* As = A_sm[cur];
        const float* Bs = B_sm[cur];
        #pragma unroll
        for (int ks = 0; ks < 4; ks++) {
            const int k = ks * 8;
            uint32_t a[4][4], b[NF][2];
            #pragma unroll
            for (int mt = 0; mt < 4; mt++) {
                const float* ap = As + (wm + mt * 16 + gq) * SPAD + k + q;
                a[mt][0] = __float_as_uint(ap[0]);
                a[mt][1] = __float_as_uint(ap[8 * SPAD]);
                a[mt][2] = __float_as_uint(ap[4]);
                a[mt][3] = __float_as_uint(ap[8 * SPAD + 4]);
            }
            #pragma unroll
            for (int nt = 0; nt < NF; nt++) {
                const float* bp = Bs + (wn + nt * 8 + gq) * SPAD + k + q;
                b[nt][0] = __float_as_uint(bp[0]);
                b[nt][1] = __float_as_uint(bp[4]);
            }
            #pragma unroll
            for (int mt = 0; mt < 4; mt++)
                #pragma unroll
                for (int nt = 0; nt < NF; nt++)
                    mma_tf32(c[mt][nt], a[mt], b[nt]);
        }
        __syncthreads();
    }

    // ------------- epilogue ---------------------------------------------------
    #pragma unroll
    for (int mt = 0; mt < 4; mt++) {
        #pragma unroll
        for (int nt = 0; nt < NF; nt++) {
            const int m = m0 + wm + mt * 16 + gq;
            const int n = n0 + wn + nt * 8 + 2 * q;
            float v00 = c[mt][nt][0], v01 = c[mt][nt][1];
            float v10 = c[mt][nt][2], v11 = c[mt][nt][3];
            if (MODE == 2) {
                v00 *= g.scale; v01 *= g.scale; v10 *= g.scale; v11 *= g.scale;
            }
            if (MODE == 0 || MODE == 1 || MODE == 4 || MODE == 5) {
                float bx = g.bias[n], by = g.bias[n + 1];
                v00 += bx; v01 += by; v10 += bx; v11 += by;
            }
            if (MODE == 4) {
                v00 = fmaxf(v00, 0.f); v01 = fmaxf(v01, 0.f);
                v10 = fmaxf(v10, 0.f); v11 = fmaxf(v11, 0.f);
            }
            if (MODE == 5) {
                const float* r0 = g.resid + (size_t)m * g.ldc + n;
                v00 += r0[0]; v01 += r0[1];
                const float* r1 = g.resid + (size_t)(m + 8) * g.ldc + n;
                v10 += r1[0]; v11 += r1[1];
            }
            if (MODE == 1) {
                // V transposed: [B,H,D,S]; idx = b*262144 + h*32768 + d*512 + s
                #pragma unroll
                for (int jj = 0; jj < 2; jj++) {
                    int nn = n + jj;
                    size_t base = (size_t)(m >> 9) * 262144 + (size_t)(nn >> 6) * 32768 +
                                  (size_t)(nn & 63) * 512;
                    g.C[base + (m & 511)]       = jj ? v01 : v00;
                    g.C[base + ((m + 8) & 511)] = jj ? v11 : v10;
                }
            } else {
                float* dst;
                if (MODE == 2)
                    dst = g.C + (size_t)z * (S_ * S_) + (size_t)m * S_ + n;
                else if (MODE == 3)
                    dst = g.C + (size_t)(z >> 3) * (S_ * E_) + (size_t)m * E_ + (z & 7) * 64 + n;
                else
                    dst = g.C + (size_t)m * g.ldc + n;
                float2 o0 = { v00, v01 }, o1 = { v10, v11 };
                *(float2*)dst = o0;
                *(float2*)(dst + (size_t)8 * ((MODE == 2) ? S_ : (MODE == 3) ? E_ : g.ldc)) = o1;
            }
        }
    }
}

// ---------------- weight transpose: src [K,N] -> dst [N,K], z-batched --------
__global__ void transpose_kernel(const float* __restrict__ src, float* __restrict__ dst,
                                 int K, int N) {
    __shared__ float t[32][33];
    int z = blockIdx.z;
    src += (size_t)z * K * N;
    dst += (size_t)z * N * K;
    int n0 = blockIdx.x * 32, k0 = blockIdx.y * 32;
    for (int i = threadIdx.y; i < 32; i += 8)
        t[i][threadIdx.x] = src[(size_t)(k0 + i) * N + n0 + threadIdx.x];
    __syncthreads();
    for (int i = threadIdx.y; i < 32; i += 8)
        dst[(size_t)(n0 + i) * K + k0 + threadIdx.x] = t[threadIdx.x][i];
}

// ---------------- embedding gather + mask ------------------------------------
__global__ void embed_kernel(const int* __restrict__ tokens, const float* __restrict__ emb) {
    int idx = blockIdx.x * 256 + threadIdx.x;
    int e = idx & (E_ - 1);
    int m = idx >> 9;
    int t = tokens[m];
    g_out[idx] = (t > 0) ? emb[t * E_ + e] : 0.0f;
}

// ---------------- row softmax over 512 (128 thr, float4 + shfl) --------------
__global__ void softmax512_kernel() {
    size_t row = blockIdx.x;
    float4* p = reinterpret_cast<float4*>(g_sc) + row * 128;
    int t = threadIdx.x;
    float4 v = p[t];
    float m = fmaxf(fmaxf(v.x, v.y), fmaxf(v.z, v.w));
    #pragma unroll
    for (int o = 16; o; o >>= 1) m = fmaxf(m, __shfl_xor_sync(0xFFFFFFFFu, m, o));
    __shared__ float sm4[4], ss4[4];
    if ((t & 31) == 0) sm4[t >> 5] = m;
    __syncthreads();
    float mx = fmaxf(fmaxf(sm4[0], sm4[1]), fmaxf(sm4[2], sm4[3]));
    v.x = expf(v.x - mx); v.y = expf(v.y - mx);
    v.z = expf(v.z - mx); v.w = expf(v.w - mx);
    float s = v.x + v.y + v.z + v.w;
    #pragma unroll
    for (int o = 16; o; o >>= 1) s += __shfl_xor_sync(0xFFFFFFFFu, s, o);
    if ((t & 31) == 0) ss4[t >> 5] = s;
    __syncthreads();
    float inv = 1.0f / (ss4[0] + ss4[1] + ss4[2] + ss4[3]);
    v.x *= inv; v.y *= inv; v.z *= inv; v.w *= inv;
    p[t] = v;
}

// ---------------- residual add + l2 normalize --------------------------------
__global__ void addnorm_kernel() {
    int row = blockIdx.x;
    float* o = g_out + (size_t)row * E_;
    const float* mh = g_mh + (size_t)row * E_;
    int t = threadIdx.x;
    float x0 = o[t] + mh[t];
    float x1 = o[t + 256] + mh[t + 256];
    __shared__ float red[256];
    red[t] = x0 * x0 + x1 * x1;
    __syncthreads();
    for (int s = 128; s > 0; s >>= 1) {
        if (t < s) red[t] += red[t + s];
        __syncthreads();
    }
    float inv = rsqrtf(fmaxf(red[0], 1e-12f));
    o[t] = x0 * inv;
    o[t + 256] = x1 * inv;
}

// ---------------- conv1d(KW=5, stride=5) -------------------------------------
__global__ void conv_kernel(const float* __restrict__ Wc, const float* __restrict__ bc) {
    int b = blockIdx.x / LOUT_;
    int j = blockIdx.x % LOUT_;
    const float* base = g_out + ((size_t)b * S_ + j * STRIDE_) * E_;
    float acc = 0.0f;
    for (int i = threadIdx.x; i < KW_ * E_; i += 256)
        acc += base[i] * Wc[i];
    __shared__ float red[256];
    red[threadIdx.x] = acc;
    __syncthreads();
    for (int s = 128; s > 0; s >>= 1) {
        if (threadIdx.x < s) red[threadIdx.x] += red[threadIdx.x + s];
        __syncthreads();
    }
    if (threadIdx.x == 0) g_pooled[b * LOUT_ + j] = red[0] + bc[0];
}

// ---------------- final dense + softmax over 1000 ----------------------------
__global__ void dense_softmax_kernel(const float* __restrict__ Wd,
                                     const float* __restrict__ bd,
                                     float* __restrict__ outp) {
    int b = blockIdx.x;
    __shared__ float p[LOUT_];
    int t = threadIdx.x;
    if (t < LOUT_) p[t] = g_pooled[b * LOUT_ + t];
    __syncthreads();

    float lg[4];
    #pragma unroll
    for (int u = 0; u < 4; u++) {
        int o = t + u * 256;
        float acc = -1e30f;
        if (o < O_) {
            acc = bd[o];
            for (int j = 0; j < LOUT_; j++)
                acc += p[j] * Wd[j * O_ + o];
        }
        lg[u] = acc;
    }
    __shared__ float red[256];
    float m = fmaxf(fmaxf(lg[0], lg[1]), fmaxf(lg[2], lg[3]));
    red[t] = m;
    __syncthreads();
    for (int s = 128; s > 0; s >>= 1) {
        if (t < s) red[t] = fmaxf(red[t], red[t + s]);
        __syncthreads();
    }
    float mx = red[0];
    __syncthreads();
    float e[4], sum = 0.0f;
    #pragma unroll
    for (int u = 0; u < 4; u++) {
        e[u] = expf(lg[u] - mx);
        sum += e[u];
    }
    red[t] = sum;
    __syncthreads();
    for (int s = 128; s > 0; s >>= 1) {
        if (t < s) red[t] += red[t + s];
        __syncthreads();
    }
    float inv = 1.0f / red[0];
    #pragma unroll
    for (int u = 0; u < 4; u++) {
        int o = t + u * 256;
        if (o < O_) outp[(size_t)b * O_ + o] = e[u] * inv;
    }
}

// ---------------- host launcher ----------------------------------------------
static const int SMEM_NT128 = 2 * (128 * SPAD + 128 * SPAD) * 4;  // 73728
static const int SMEM_NT64  = 2 * (128 * SPAD + 64 * SPAD) * 4;   // 55296

extern "C" void kernel_launch(void* const* d_in, const int* in_sizes, int n_in,
                              void* d_out, int out_size) {
    const int*   tokens = (const int*)  d_in[0];
    const float* emb    = (const float*)d_in[1];
    const float* Wq     = (const float*)d_in[2];
    const float* bq     = (const float*)d_in[3];
    const float* Wk     = (const float*)d_in[4];
    const float* bk     = (const float*)d_in[5];
    const float* Wv     = (const float*)d_in[6];
    const float* bv     = (const float*)d_in[7];
    const float* Wo     = (const float*)d_in[8];
    const float* bo     = (const float*)d_in[9];
    const float* W1     = (const float*)d_in[10];
    const float* b1     = (const float*)d_in[11];
    const float* W2     = (const float*)d_in[12];
    const float* b2     = (const float*)d_in[13];
    const float* Wc     = (const float*)d_in[14];
    const float* bc     = (const float*)d_in[15];
    const float* Wd     = (const float*)d_in[16];
    const float* bd     = (const float*)d_in[17];
    float* outp = (float*)d_out;
    (void)in_sizes; (void)n_in; (void)out_size;

    float *p_out, *p_q, *p_k, *p_vt, *p_sc, *p_cat, *p_mh, *p_ff, *p_wt;
    cudaGetSymbolAddress((void**)&p_out, g_out);
    cudaGetSymbolAddress((void**)&p_q,   g_q);
    cudaGetSymbolAddress((void**)&p_k,   g_k);
    cudaGetSymbolAddress((void**)&p_vt,  g_vt);
    cudaGetSymbolAddress((void**)&p_sc,  g_sc);
    cudaGetSymbolAddress((void**)&p_cat, g_cat);
    cudaGetSymbolAddress((void**)&p_mh,  g_mh);
    cudaGetSymbolAddress((void**)&p_ff,  g_ff);
    cudaGetSymbolAddress((void**)&p_wt,  g_wt);

    cudaFuncSetAttribute(gemmT<0,128,16>, cudaFuncAttributeMaxDynamicSharedMemorySize, SMEM_NT128);
    cudaFuncSetAttribute(gemmT<1,128,16>, cudaFuncAttributeMaxDynamicSharedMemorySize, SMEM_NT128);
    cudaFuncSetAttribute(gemmT<2,128,2>,  cudaFuncAttributeMaxDynamicSharedMemorySize, SMEM_NT128);
    cudaFuncSetAttribute(gemmT<3,64,16>,  cudaFuncAttributeMaxDynamicSharedMemorySize, SMEM_NT64);
    cudaFuncSetAttribute(gemmT<4,128,16>, cudaFuncAttributeMaxDynamicSharedMemorySize, SMEM_NT128);
    cudaFuncSetAttribute(gemmT<5,128,32>, cudaFuncAttributeMaxDynamicSharedMemorySize, SMEM_NT128);

    const float scale = 0.044194173824159216f;  // 1/sqrt(512)
    dim3 tthr(32, 8);

    // ---- pre-transpose all weights to [N,K] ----
    for (int i = 0; i < L_; i++) {
        float* wt = p_wt + (size_t)i * LWT_;
        transpose_kernel<<<dim3(2, 16, 8), tthr>>>(Wq + (size_t)i*H_*E_*D_, wt + QT_,  512, 64);
        transpose_kernel<<<dim3(2, 16, 8), tthr>>>(Wk + (size_t)i*H_*E_*D_, wt + KT_,  512, 64);
        transpose_kernel<<<dim3(2, 16, 8), tthr>>>(Wv + (size_t)i*H_*E_*D_, wt + VTW_, 512, 64);
        transpose_kernel<<<dim3(16, 16, 1), tthr>>>(Wo + (size_t)i*E_*E_,   wt + OT_,  512, 512);
        transpose_kernel<<<dim3(32, 16, 1), tthr>>>(W1 + (size_t)i*E_*2*E_, wt + W1T_, 512, 1024);
        transpose_kernel<<<dim3(16, 32, 1), tthr>>>(W2 + (size_t)i*2*E_*E_, wt + W2T_, 1024, 512);
    }

    embed_kernel<<<(M_ * E_) / 256, 256>>>(tokens, emb);

    for (int i = 0; i < L_; i++) {
        float* wt = p_wt + (size_t)i * LWT_;
        GArgs a;

        // Q = out @ Wq^T + bq   -> [B,S,H*D]
        a = { p_out, wt + QT_, p_q, bq + (size_t)i*512, nullptr, 512, 512, 512, 1.0f };
        gemmT<0,128,16><<<dim3(4, 256, 1), 256, SMEM_NT128>>>(a);
        // K
        a = { p_out, wt + KT_, p_k, bk + (size_t)i*512, nullptr, 512, 512, 512, 1.0f };
        gemmT<0,128,16><<<dim3(4, 256, 1), 256, SMEM_NT128>>>(a);
        // V (written transposed -> [B,H,D,S])
        a = { p_out, wt + VTW_, p_vt, bv + (size_t)i*512, nullptr, 512, 512, 512, 1.0f };
        gemmT<1,128,16><<<dim3(4, 256, 1), 256, SMEM_NT128>>>(a);

        // scores = Q @ K^T * scale   (z = b*8+h)
        a = { p_q, p_k, p_sc, nullptr, nullptr, 512, 512, 512, scale };
        gemmT<2,128,2><<<dim3(4, 4, 512), 256, SMEM_NT128>>>(a);

        softmax512_kernel<<<BH_ * S_, 128>>>();

        // cat = attn @ V   -> [B,S,H*D]
        a = { p_sc, p_vt, p_cat, nullptr, nullptr, 512, 512, 512, 1.0f };
        gemmT<3,64,16><<<dim3(1, 4, 512), 256, SMEM_NT64>>>(a);

        // mh = cat @ Wo^T + bo
        a = { p_cat, wt + OT_, p_mh, bo + (size_t)i*512, nullptr, 512, 512, 512, 1.0f };
        gemmT<0,128,16><<<dim3(4, 256, 1), 256, SMEM_NT128>>>(a);

        addnorm_kernel<<<M_, 256>>>();

        // ff = relu(out @ W1^T + b1)
        a = { p_out, wt + W1T_, p_ff, b1 + (size_t)i*1024, nullptr, 512, 512, 1024, 1.0f };
        gemmT<4,128,16><<<dim3(8, 256, 1), 256, SMEM_NT128>>>(a);

        // out = ff @ W2^T + b2 + out
        a = { p_ff, wt + W2T_, p_out, b2 + (size_t)i*512, p_out, 1024, 1024, 512, 1.0f };
        gemmT<5,128,32><<<dim3(4, 256, 1), 256, SMEM_NT128>>>(a);
    }

    conv_kernel<<<B_ * LOUT_, 256>>>(Wc, bc);
    dense_softmax_kernel<<<B_, 256>>>(Wd, bd, outp);
}

// round 6
// speedup vs baseline: 4.1860x; 1.1110x over previous
#include <cuda_runtime.h>
#include <cstdint>
#include <math.h>

#define B_ 64
#define S_ 512
#define E_ 512
#define H_ 8
#define D_ 64
#define L_ 4
#define O_ 1000
#define KW_ 5
#define STRIDE_ 5
#define LOUT_ 102
#define BH_ (B_*H_)
#define M_ (B_*S_)   /* 32768 */

// ---------------- scratch ----------------------------------------------------
__device__ float g_out[M_*E_];              // activations [B,S,E]
__device__ float g_q[M_*E_];                // [B,S,H*D]
__device__ float g_k[M_*E_];                // [B,S,H*D]
__device__ float g_vt[M_*E_];               // [B,H,D,S]  (pre-transposed V)
__device__ float g_cat[M_*E_];              // [B,S,H*D]
__device__ float g_mh[M_*E_];
__device__ float g_ff[M_*2*E_];
__device__ float g_pooled[B_*LOUT_];
#define LWT_ 2097152
__device__ float g_wt[(size_t)L_*LWT_];     // transposed weights per layer
#define QT_  0
#define KT_  262144
#define VTW_ 524288
#define OT_  786432
#define W1T_ 1048576
#define W2T_ 1572864

// ---------------- helpers -----------------------------------------------------
__device__ __forceinline__ uint32_t smem_u32(const void* p) {
    uint32_t a;
    asm("{ .reg .u64 t; cvta.to.shared.u64 t, %1; cvt.u32.u64 %0, t; }" : "=r"(a) : "l"(p));
    return a;
}
__device__ __forceinline__ void cp_async16(uint32_t dst, const void* src) {
    asm volatile("cp.async.cg.shared.global [%0], [%1], 16;" :: "r"(dst), "l"(src) : "memory");
}
__device__ __forceinline__ void cp_commit() {
    asm volatile("cp.async.commit_group;" ::: "memory");
}
__device__ __forceinline__ void cp_wait0() {
    asm volatile("cp.async.wait_group 0;" ::: "memory");
}
__device__ __forceinline__ void cp_wait1() {
    asm volatile("cp.async.wait_group 1;" ::: "memory");
}
__device__ __forceinline__ void mma_tf32(float* c, const uint32_t* a, const uint32_t* b) {
    asm volatile(
        "mma.sync.aligned.m16n8k8.row.col.f32.tf32.tf32.f32 "
        "{%0,%1,%2,%3}, {%4,%5,%6,%7}, {%8,%9}, {%0,%1,%2,%3};"
        : "+f"(c[0]), "+f"(c[1]), "+f"(c[2]), "+f"(c[3])
        : "r"(a[0]), "r"(a[1]), "r"(a[2]), "r"(a[3]), "r"(b[0]), "r"(b[1]));
}

// smem row stride 36 floats: bank = 4*row + col (mod 32) -> conflict-free frags
#define SPAD 36

// async tile loader: R rows x 32 fp32 cols from src (row stride ld)
template<int R>
__device__ __forceinline__ void load_tile(float* sm, const float* __restrict__ src, int ld) {
    const int t = threadIdx.x;
    #pragma unroll
    for (int i = 0; i < (R * 8) / 256; i++) {
        int idx = t + i * 256;
        int r = idx >> 3, c4 = idx & 7;
        cp_async16(smem_u32(sm + r * SPAD + c4 * 4), src + (size_t)r * ld + c4 * 4);
    }
}

// ---------------- tf32 mma.sync GEMM -----------------------------------------
// MODE: 0=PROJ(bias), 1=VPROJ(bias, transposed C), 4=FFN1(bias+relu), 5=FFN2(bias+resid)
struct GArgs {
    const float* A; const float* B; float* C;
    const float* bias; const float* resid;
    int lda, ldb, ldc; float scale;
};

template<int MODE, int NT, int NC>
__global__ __launch_bounds__(256) void gemmT(GArgs g) {
    extern __shared__ float sm[];
    constexpr int NF = NT / 32;               // n-frags per warp (4 or 2)
    constexpr int ASZ = 128 * SPAD;
    constexpr int BSZ = NT * SPAD;
    float* A_sm[2] = { sm, sm + ASZ };
    float* B_sm[2] = { sm + 2 * ASZ, sm + 2 * ASZ + BSZ };

    const int tid = threadIdx.x;
    const int w = tid >> 5, lane = tid & 31;
    const int gq = lane >> 2, q = lane & 3;
    const int wm = (w >> 2) * 64;
    const int wn = (w & 3) * (NT / 4);

    const int m0 = blockIdx.y * 128, n0 = blockIdx.x * NT;
    const float* Ab = g.A + (size_t)m0 * g.lda;
    const float* Bb = g.B + (size_t)n0 * g.ldb;

    float c[4][NF][4];
    #pragma unroll
    for (int mt = 0; mt < 4; mt++)
        #pragma unroll
        for (int nt = 0; nt < NF; nt++)
            #pragma unroll
            for (int j = 0; j < 4; j++) c[mt][nt][j] = 0.0f;

    load_tile<128>(A_sm[0], Ab, g.lda);
    load_tile<NT>(B_sm[0], Bb, g.ldb);
    cp_commit();

    #pragma unroll 1
    for (int ch = 0; ch < NC; ch++) {
        const int cur = ch & 1;
        cp_wait0();
        __syncthreads();
        if (ch + 1 < NC) {
            load_tile<128>(A_sm[cur ^ 1], Ab + (ch + 1) * 32, g.lda);
            load_tile<NT>(B_sm[cur ^ 1], Bb + (ch + 1) * 32, g.ldb);
            cp_commit();
        }
        const float* As = A_sm[cur];
        const float* Bs = B_sm[cur];
        #pragma unroll
        for (int ks = 0; ks < 4; ks++) {
            const int k = ks * 8;
            uint32_t a[4][4], b[NF][2];
            #pragma unroll
            for (int mt = 0; mt < 4; mt++) {
                const float* ap = As + (wm + mt * 16 + gq) * SPAD + k + q;
                a[mt][0] = __float_as_uint(ap[0]);
                a[mt][1] = __float_as_uint(ap[8 * SPAD]);
                a[mt][2] = __float_as_uint(ap[4]);
                a[mt][3] = __float_as_uint(ap[8 * SPAD + 4]);
            }
            #pragma unroll
            for (int nt = 0; nt < NF; nt++) {
                const float* bp = Bs + (wn + nt * 8 + gq) * SPAD + k + q;
                b[nt][0] = __float_as_uint(bp[0]);
                b[nt][1] = __float_as_uint(bp[4]);
            }
            #pragma unroll
            for (int mt = 0; mt < 4; mt++)
                #pragma unroll
                for (int nt = 0; nt < NF; nt++)
                    mma_tf32(c[mt][nt], a[mt], b[nt]);
        }
        __syncthreads();
    }

    // ------------- epilogue ---------------------------------------------------
    #pragma unroll
    for (int mt = 0; mt < 4; mt++) {
        #pragma unroll
        for (int nt = 0; nt < NF; nt++) {
            const int m = m0 + wm + mt * 16 + gq;
            const int n = n0 + wn + nt * 8 + 2 * q;
            float v00 = c[mt][nt][0], v01 = c[mt][nt][1];
            float v10 = c[mt][nt][2], v11 = c[mt][nt][3];
            {
                float bx = g.bias[n], by = g.bias[n + 1];
                v00 += bx; v01 += by; v10 += bx; v11 += by;
            }
            if (MODE == 4) {
                v00 = fmaxf(v00, 0.f); v01 = fmaxf(v01, 0.f);
                v10 = fmaxf(v10, 0.f); v11 = fmaxf(v11, 0.f);
            }
            if (MODE == 5) {
                const float* r0 = g.resid + (size_t)m * g.ldc + n;
                v00 += r0[0]; v01 += r0[1];
                const float* r1 = g.resid + (size_t)(m + 8) * g.ldc + n;
                v10 += r1[0]; v11 += r1[1];
            }
            if (MODE == 1) {
                // V transposed: [B,H,D,S]; idx = b*262144 + h*32768 + d*512 + s
                #pragma unroll
                for (int jj = 0; jj < 2; jj++) {
                    int nn = n + jj;
                    size_t base = (size_t)(m >> 9) * 262144 + (size_t)(nn >> 6) * 32768 +
                                  (size_t)(nn & 63) * 512;
                    g.C[base + (m & 511)]       = jj ? v01 : v00;
                    g.C[base + ((m + 8) & 511)] = jj ? v11 : v10;
                }
            } else {
                float* dst = g.C + (size_t)m * g.ldc + n;
                float2 o0 = { v00, v01 }, o1 = { v10, v11 };
                *(float2*)dst = o0;
                *(float2*)(dst + (size_t)8 * g.ldc) = o1;
            }
        }
    }
}

// ---------------- fused flash attention --------------------------------------
// grid (S_/128, BH_), 256 threads. Q tile 128 rows x 64; loop 4 K/V tiles of 128.
// smem: K[2]:128x68, V[2]:64x132 (Vt: [d][s]), P:128x132 (also Q staging)
#define SPK 68
#define SPV 132
#define FL_SMEM ((2*128*SPK + 2*64*SPV + 128*SPV) * 4)   /* 204800 B */

__global__ __launch_bounds__(256) void flash_kernel(float scale) {
    extern __shared__ float sm[];
    constexpr int KSZ = 128 * SPK, VSZ = 64 * SPV;
    float* Ks[2] = { sm, sm + KSZ };
    float* Vs[2] = { sm + 2 * KSZ, sm + 2 * KSZ + VSZ };
    float* Ps = sm + 2 * KSZ + 2 * VSZ;

    const int tid = threadIdx.x, w = tid >> 5, lane = tid & 31;
    const int gq = lane >> 2, q = lane & 3;
    const int z = blockIdx.y, b = z >> 3, h = z & 7;
    const int q0 = blockIdx.x * 128;

    const float* Qg = g_q + ((size_t)b * S_ + q0) * E_ + h * 64;
    const float* Kg = g_k + (size_t)b * S_ * E_ + h * 64;
    const float* Vg = g_vt + (size_t)z * (64 * S_);

    // stage Q tile into Ps (coalesced), then pick up as A-fragments
    for (int i = tid; i < 128 * 16; i += 256) {
        int r = i >> 4, c4 = i & 15;
        cp_async16(smem_u32(Ps + r * SPV + c4 * 4), Qg + (size_t)r * E_ + c4 * 4);
    }
    cp_commit();
    // prefetch K/V tile 0
    for (int i = tid; i < 128 * 16; i += 256) {
        int r = i >> 4, c4 = i & 15;
        cp_async16(smem_u32(Ks[0] + r * SPK + c4 * 4), Kg + (size_t)r * E_ + c4 * 4);
    }
    for (int i = tid; i < 64 * 32; i += 256) {
        int r = i >> 5, c4 = i & 31;
        cp_async16(smem_u32(Vs[0] + r * SPV + c4 * 4), Vg + (size_t)r * S_ + c4 * 4);
    }
    cp_commit();

    cp_wait1();          // Q staged (KV0 may still be in flight)
    __syncthreads();

    uint32_t qf[8][4];
    {
        const float* ap0 = Ps + (w * 16 + gq) * SPV + q;
        #pragma unroll
        for (int kf = 0; kf < 8; kf++) {
            const float* ap = ap0 + kf * 8;
            qf[kf][0] = __float_as_uint(ap[0]);
            qf[kf][1] = __float_as_uint(ap[8 * SPV]);
            qf[kf][2] = __float_as_uint(ap[4]);
            qf[kf][3] = __float_as_uint(ap[8 * SPV + 4]);
        }
    }

    float o[8][4];
    #pragma unroll
    for (int i = 0; i < 8; i++)
        #pragma unroll
        for (int j = 0; j < 4; j++) o[i][j] = 0.0f;
    float mr0 = -1e30f, mr1 = -1e30f, l0 = 0.0f, l1 = 0.0f;

    #pragma unroll 1
    for (int kt = 0; kt < 4; kt++) {
        const int cur = kt & 1;
        cp_wait0();
        __syncthreads();
        if (kt < 3) {
            const int nxt = cur ^ 1;
            const float* Kn = Kg + (size_t)(kt + 1) * 128 * E_;
            for (int i = tid; i < 128 * 16; i += 256) {
                int r = i >> 4, c4 = i & 15;
                cp_async16(smem_u32(Ks[nxt] + r * SPK + c4 * 4), Kn + (size_t)r * E_ + c4 * 4);
            }
            const float* Vn = Vg + (kt + 1) * 128;
            for (int i = tid; i < 64 * 32; i += 256) {
                int r = i >> 5, c4 = i & 31;
                cp_async16(smem_u32(Vs[nxt] + r * SPV + c4 * 4), Vn + (size_t)r * S_ + c4 * 4);
            }
            cp_commit();
        }

        // ---- S = Q @ K^T  (per warp: 16 q-rows x 128 keys) ----
        float s[16][4];
        #pragma unroll
        for (int nf = 0; nf < 16; nf++)
            #pragma unroll
            for (int j = 0; j < 4; j++) s[nf][j] = 0.0f;
        #pragma unroll
        for (int kf = 0; kf < 8; kf++) {
            #pragma unroll
            for (int nf = 0; nf < 16; nf++) {
                const float* bp = Ks[cur] + (nf * 8 + gq) * SPK + kf * 8 + q;
                uint32_t bb[2] = { __float_as_uint(bp[0]), __float_as_uint(bp[4]) };
                mma_tf32(s[nf], qf[kf], bb);
            }
        }

        // ---- scale + row max (rows gq / gq+8 live on 4 quad lanes) ----
        float mt0 = -1e30f, mt1 = -1e30f;
        #pragma unroll
        for (int nf = 0; nf < 16; nf++) {
            s[nf][0] *= scale; s[nf][1] *= scale;
            s[nf][2] *= scale; s[nf][3] *= scale;
            mt0 = fmaxf(mt0, fmaxf(s[nf][0], s[nf][1]));
            mt1 = fmaxf(mt1, fmaxf(s[nf][2], s[nf][3]));
        }
        mt0 = fmaxf(mt0, __shfl_xor_sync(0xFFFFFFFFu, mt0, 1));
        mt0 = fmaxf(mt0, __shfl_xor_sync(0xFFFFFFFFu, mt0, 2));
        mt1 = fmaxf(mt1, __shfl_xor_sync(0xFFFFFFFFu, mt1, 1));
        mt1 = fmaxf(mt1, __shfl_xor_sync(0xFFFFFFFFu, mt1, 2));

        float mn0 = fmaxf(mr0, mt0), mn1 = fmaxf(mr1, mt1);
        float al0 = __expf(mr0 - mn0), al1 = __expf(mr1 - mn1);

        // ---- P = exp(S - m), store to warp-local smem rows, row sums ----
        float sum0 = 0.0f, sum1 = 0.0f;
        float* prow = Ps + (w * 16 + gq) * SPV + 2 * q;
        #pragma unroll
        for (int nf = 0; nf < 16; nf++) {
            float p0 = __expf(s[nf][0] - mn0), p1 = __expf(s[nf][1] - mn0);
            float p2 = __expf(s[nf][2] - mn1), p3 = __expf(s[nf][3] - mn1);
            sum0 += p0 + p1; sum1 += p2 + p3;
            float2 t0 = { p0, p1 }, t1 = { p2, p3 };
            *(float2*)(prow + nf * 8) = t0;
            *(float2*)(prow + nf * 8 + 8 * SPV) = t1;
        }
        sum0 += __shfl_xor_sync(0xFFFFFFFFu, sum0, 1);
        sum0 += __shfl_xor_sync(0xFFFFFFFFu, sum0, 2);
        sum1 += __shfl_xor_sync(0xFFFFFFFFu, sum1, 1);
        sum1 += __shfl_xor_sync(0xFFFFFFFFu, sum1, 2);
        l0 = l0 * al0 + sum0;
        l1 = l1 * al1 + sum1;
        mr0 = mn0; mr1 = mn1;

        #pragma unroll
        for (int nf2 = 0; nf2 < 8; nf2++) {
            o[nf2][0] *= al0; o[nf2][1] *= al0;
            o[nf2][2] *= al1; o[nf2][3] *= al1;
        }
        __syncwarp();

        // ---- O += P @ V ----
        #pragma unroll
        for (int kf2 = 0; kf2 < 16; kf2++) {
            const float* ap = Ps + (w * 16 + gq) * SPV + kf2 * 8 + q;
            uint32_t aa[4] = { __float_as_uint(ap[0]), __float_as_uint(ap[8 * SPV]),
                               __float_as_uint(ap[4]), __float_as_uint(ap[8 * SPV + 4]) };
            #pragma unroll
            for (int nf2 = 0; nf2 < 8; nf2++) {
                const float* bp = Vs[cur] + (nf2 * 8 + gq) * SPV + kf2 * 8 + q;
                uint32_t bb[2] = { __float_as_uint(bp[0]), __float_as_uint(bp[4]) };
                mma_tf32(o[nf2], aa, bb);
            }
        }
        __syncwarp();
    }

    // ---- epilogue: O / l -> g_cat[b, s, h*64+d] ----
    float li0 = 1.0f / l0, li1 = 1.0f / l1;
    const int m = q0 + w * 16 + gq;
    float* dst = g_cat + ((size_t)b * S_ + m) * E_ + h * 64 + 2 * q;
    #pragma unroll
    for (int nf2 = 0; nf2 < 8; nf2++) {
        float2 t0 = { o[nf2][0] * li0, o[nf2][1] * li0 };
        float2 t1 = { o[nf2][2] * li1, o[nf2][3] * li1 };
        *(float2*)(dst + nf2 * 8) = t0;
        *(float2*)(dst + nf2 * 8 + (size_t)8 * E_) = t1;
    }
}

// ---------------- weight transpose: src [K,N] -> dst [N,K], z-batched --------
__global__ void transpose_kernel(const float* __restrict__ src, float* __restrict__ dst,
                                 int K, int N) {
    __shared__ float t[32][33];
    int z = blockIdx.z;
    src += (size_t)z * K * N;
    dst += (size_t)z * N * K;
    int n0 = blockIdx.x * 32, k0 = blockIdx.y * 32;
    for (int i = threadIdx.y; i < 32; i += 8)
        t[i][threadIdx.x] = src[(size_t)(k0 + i) * N + n0 + threadIdx.x];
    __syncthreads();
    for (int i = threadIdx.y; i < 32; i += 8)
        dst[(size_t)(n0 + i) * K + k0 + threadIdx.x] = t[threadIdx.x][i];
}

// ---------------- embedding gather + mask ------------------------------------
__global__ void embed_kernel(const int* __restrict__ tokens, const float* __restrict__ emb) {
    int idx = blockIdx.x * 256 + threadIdx.x;
    int e = idx & (E_ - 1);
    int m = idx >> 9;
    int t = tokens[m];
    g_out[idx] = (t > 0) ? emb[t * E_ + e] : 0.0f;
}

// ---------------- residual add + l2 normalize --------------------------------
__global__ void addnorm_kernel() {
    int row = blockIdx.x;
    float* o = g_out + (size_t)row * E_;
    const float* mh = g_mh + (size_t)row * E_;
    int t = threadIdx.x;
    float x0 = o[t] + mh[t];
    float x1 = o[t + 256] + mh[t + 256];
    __shared__ float red[256];
    red[t] = x0 * x0 + x1 * x1;
    __syncthreads();
    for (int s = 128; s > 0; s >>= 1) {
        if (t < s) red[t] += red[t + s];
        __syncthreads();
    }
    float inv = rsqrtf(fmaxf(red[0], 1e-12f));
    o[t] = x0 * inv;
    o[t + 256] = x1 * inv;
}

// ---------------- conv1d(KW=5, stride=5) -------------------------------------
__global__ void conv_kernel(const float* __restrict__ Wc, const float* __restrict__ bc) {
    int b = blockIdx.x / LOUT_;
    int j = blockIdx.x % LOUT_;
    const float* base = g_out + ((size_t)b * S_ + j * STRIDE_) * E_;
    float acc = 0.0f;
    for (int i = threadIdx.x; i < KW_ * E_; i += 256)
        acc += base[i] * Wc[i];
    __shared__ float red[256];
    red[threadIdx.x] = acc;
    __syncthreads();
    for (int s = 128; s > 0; s >>= 1) {
        if (threadIdx.x < s) red[threadIdx.x] += red[threadIdx.x + s];
        __syncthreads();
    }
    if (threadIdx.x == 0) g_pooled[b * LOUT_ + j] = red[0] + bc[0];
}

// ---------------- final dense + softmax over 1000 ----------------------------
__global__ void dense_softmax_kernel(const float* __restrict__ Wd,
                                     const float* __restrict__ bd,
                                     float* __restrict__ outp) {
    int b = blockIdx.x;
    __shared__ float p[LOUT_];
    int t = threadIdx.x;
    if (t < LOUT_) p[t] = g_pooled[b * LOUT_ + t];
    __syncthreads();

    float lg[4];
    #pragma unroll
    for (int u = 0; u < 4; u++) {
        int o = t + u * 256;
        float acc = -1e30f;
        if (o < O_) {
            acc = bd[o];
            for (int j = 0; j < LOUT_; j++)
                acc += p[j] * Wd[j * O_ + o];
        }
        lg[u] = acc;
    }
    __shared__ float red[256];
    float m = fmaxf(fmaxf(lg[0], lg[1]), fmaxf(lg[2], lg[3]));
    red[t] = m;
    __syncthreads();
    for (int s = 128; s > 0; s >>= 1) {
        if (t < s) red[t] = fmaxf(red[t], red[t + s]);
        __syncthreads();
    }
    float mx = red[0];
    __syncthreads();
    float e[4], sum = 0.0f;
    #pragma unroll
    for (int u = 0; u < 4; u++) {
        e[u] = expf(lg[u] - mx);
        sum += e[u];
    }
    red[t] = sum;
    __syncthreads();
    for (int s = 128; s > 0; s >>= 1) {
        if (t < s) red[t] += red[t + s];
        __syncthreads();
    }
    float inv = 1.0f / red[0];
    #pragma unroll
    for (int u = 0; u < 4; u++) {
        int o = t + u * 256;
        if (o < O_) outp[(size_t)b * O_ + o] = e[u] * inv;
    }
}

// ---------------- host launcher ----------------------------------------------
static const int SMEM_NT128 = 2 * (128 * SPAD + 128 * SPAD) * 4;  // 73728

extern "C" void kernel_launch(void* const* d_in, const int* in_sizes, int n_in,
                              void* d_out, int out_size) {
    const int*   tokens = (const int*)  d_in[0];
    const float* emb    = (const float*)d_in[1];
    const float* Wq     = (const float*)d_in[2];
    const float* bq     = (const float*)d_in[3];
    const float* Wk     = (const float*)d_in[4];
    const float* bk     = (const float*)d_in[5];
    const float* Wv     = (const float*)d_in[6];
    const float* bv     = (const float*)d_in[7];
    const float* Wo     = (const float*)d_in[8];
    const float* bo     = (const float*)d_in[9];
    const float* W1     = (const float*)d_in[10];
    const float* b1     = (const float*)d_in[11];
    const float* W2     = (const float*)d_in[12];
    const float* b2     = (const float*)d_in[13];
    const float* Wc     = (const float*)d_in[14];
    const float* bc     = (const float*)d_in[15];
    const float* Wd     = (const float*)d_in[16];
    const float* bd     = (const float*)d_in[17];
    float* outp = (float*)d_out;
    (void)in_sizes; (void)n_in; (void)out_size;

    float *p_out, *p_q, *p_k, *p_vt, *p_cat, *p_mh, *p_ff, *p_wt;
    cudaGetSymbolAddress((void**)&p_out, g_out);
    cudaGetSymbolAddress((void**)&p_q,   g_q);
    cudaGetSymbolAddress((void**)&p_k,   g_k);
    cudaGetSymbolAddress((void**)&p_vt,  g_vt);
    cudaGetSymbolAddress((void**)&p_cat, g_cat);
    cudaGetSymbolAddress((void**)&p_mh,  g_mh);
    cudaGetSymbolAddress((void**)&p_ff,  g_ff);
    cudaGetSymbolAddress((void**)&p_wt,  g_wt);

    cudaFuncSetAttribute(gemmT<0,128,16>, cudaFuncAttributeMaxDynamicSharedMemorySize, SMEM_NT128);
    cudaFuncSetAttribute(gemmT<1,128,16>, cudaFuncAttributeMaxDynamicSharedMemorySize, SMEM_NT128);
    cudaFuncSetAttribute(gemmT<4,128,16>, cudaFuncAttributeMaxDynamicSharedMemorySize, SMEM_NT128);
    cudaFuncSetAttribute(gemmT<5,128,32>, cudaFuncAttributeMaxDynamicSharedMemorySize, SMEM_NT128);
    cudaFuncSetAttribute(flash_kernel,    cudaFuncAttributeMaxDynamicSharedMemorySize, FL_SMEM);

    const float scale = 0.044194173824159216f;  // 1/sqrt(512)
    dim3 tthr(32, 8);

    // ---- pre-transpose all weights to [N,K] ----
    for (int i = 0; i < L_; i++) {
        float* wt = p_wt + (size_t)i * LWT_;
        transpose_kernel<<<dim3(2, 16, 8), tthr>>>(Wq + (size_t)i*H_*E_*D_, wt + QT_,  512, 64);
        transpose_kernel<<<dim3(2, 16, 8), tthr>>>(Wk + (size_t)i*H_*E_*D_, wt + KT_,  512, 64);
        transpose_kernel<<<dim3(2, 16, 8), tthr>>>(Wv + (size_t)i*H_*E_*D_, wt + VTW_, 512, 64);
        transpose_kernel<<<dim3(16, 16, 1), tthr>>>(Wo + (size_t)i*E_*E_,   wt + OT_,  512, 512);
        transpose_kernel<<<dim3(32, 16, 1), tthr>>>(W1 + (size_t)i*E_*2*E_, wt + W1T_, 512, 1024);
        transpose_kernel<<<dim3(16, 32, 1), tthr>>>(W2 + (size_t)i*2*E_*E_, wt + W2T_, 1024, 512);
    }

    embed_kernel<<<(M_ * E_) / 256, 256>>>(tokens, emb);

    for (int i = 0; i < L_; i++) {
        float* wt = p_wt + (size_t)i * LWT_;
        GArgs a;

        // Q = out @ Wq^T + bq   -> [B,S,H*D]
        a = { p_out, wt + QT_, p_q, bq + (size_t)i*512, nullptr, 512, 512, 512, 1.0f };
        gemmT<0,128,16><<<dim3(4, 256, 1), 256, SMEM_NT128>>>(a);
        // K
        a = { p_out, wt + KT_, p_k, bk + (size_t)i*512, nullptr, 512, 512, 512, 1.0f };
        gemmT<0,128,16><<<dim3(4, 256, 1), 256, SMEM_NT128>>>(a);
        // V (written transposed -> [B,H,D,S])
        a = { p_out, wt + VTW_, p_vt, bv + (size_t)i*512, nullptr, 512, 512, 512, 1.0f };
        gemmT<1,128,16><<<dim3(4, 256, 1), 256, SMEM_NT128>>>(a);

        // fused attention: scores + softmax + attn@V -> g_cat
        flash_kernel<<<dim3(S_/128, BH_), 256, FL_SMEM>>>(scale);

        // mh = cat @ Wo^T + bo
        a = { p_cat, wt + OT_, p_mh, bo + (size_t)i*512, nullptr, 512, 512, 512, 1.0f };
        gemmT<0,128,16><<<dim3(4, 256, 1), 256, SMEM_NT128>>>(a);

        addnorm_kernel<<<M_, 256>>>();

        // ff = relu(out @ W1^T + b1)
        a = { p_out, wt + W1T_, p_ff, b1 + (size_t)i*1024, nullptr, 512, 512, 1024, 1.0f };
        gemmT<4,128,16><<<dim3(8, 256, 1), 256, SMEM_NT128>>>(a);

        // out = ff @ W2^T + b2 + out
        a = { p_ff, wt + W2T_, p_out, b2 + (size_t)i*512, p_out, 1024, 1024, 512, 1.0f };
        gemmT<5,128,32><<<dim3(4, 256, 1), 256, SMEM_NT128>>>(a);
    }

    conv_kernel<<<B_ * LOUT_, 256>>>(Wc, bc);
    dense_softmax_kernel<<<B_, 256>>>(Wd, bd, outp);
}

// round 7
// speedup vs baseline: 7.2090x; 1.7222x over previous
#include <cuda_runtime.h>
#include <cuda_bf16.h>
#include <cstdint>
#include <math.h>

#define B_ 64
#define S_ 512
#define E_ 512
#define H_ 8
#define D_ 64
#define L_ 4
#define O_ 1000
#define KW_ 5
#define STRIDE_ 5
#define LOUT_ 102
#define BH_ (B_*H_)
#define M_ (B_*S_)   /* 32768 */

typedef __nv_bfloat16 bf16;

// ---------------- scratch ----------------------------------------------------
__device__ float g_out[M_*E_];              // fp32 master activations [B,S,E]
__device__ float g_mh[M_*E_];               // attention block output (fp32)
__device__ float g_pooled[B_*LOUT_];
__device__ bf16  g_outb[M_*E_];             // bf16 shadow of g_out
__device__ bf16  g_qb[M_*E_];               // [B,S,H*D]
__device__ bf16  g_kb[M_*E_];               // [B,S,H*D]
__device__ bf16  g_vtb[M_*E_];              // [B,H,D,S]
__device__ bf16  g_catb[M_*E_];             // [B,S,H*D]
__device__ bf16  g_ffb[M_*2*E_];            // FFN hidden
#define LWT_ 2097152
__device__ bf16  g_wtb[(size_t)L_*LWT_];    // transposed bf16 weights per layer
#define QT_  0
#define KT_  262144
#define VTW_ 524288
#define OT_  786432
#define W1T_ 1048576
#define W2T_ 1572864

// ---------------- helpers -----------------------------------------------------
__device__ __forceinline__ uint32_t smem_u32(const void* p) {
    uint32_t a;
    asm("{ .reg .u64 t; cvta.to.shared.u64 t, %1; cvt.u32.u64 %0, t; }" : "=r"(a) : "l"(p));
    return a;
}
__device__ __forceinline__ void cp_async16(uint32_t dst, const void* src) {
    asm volatile("cp.async.cg.shared.global [%0], [%1], 16;" :: "r"(dst), "l"(src) : "memory");
}
__device__ __forceinline__ void cp_commit() {
    asm volatile("cp.async.commit_group;" ::: "memory");
}
__device__ __forceinline__ void cp_wait0() {
    asm volatile("cp.async.wait_group 0;" ::: "memory");
}
__device__ __forceinline__ void cp_wait1() {
    asm volatile("cp.async.wait_group 1;" ::: "memory");
}
__device__ __forceinline__ void mma_bf16(float* c, const uint32_t* a, const uint32_t* b) {
    asm volatile(
        "mma.sync.aligned.m16n8k16.row.col.f32.bf16.bf16.f32 "
        "{%0,%1,%2,%3}, {%4,%5,%6,%7}, {%8,%9}, {%0,%1,%2,%3};"
        : "+f"(c[0]), "+f"(c[1]), "+f"(c[2]), "+f"(c[3])
        : "r"(a[0]), "r"(a[1]), "r"(a[2]), "r"(a[3]), "r"(b[0]), "r"(b[1]));
}
__device__ __forceinline__ uint32_t packbf(float a, float b) {
    __nv_bfloat162 h = __floats2bfloat162_rn(a, b);
    return *(uint32_t*)&h;
}

// ---------------- bf16 mma GEMM ----------------------------------------------
// CTA tile 128x128, k-chunk 64 (bf16), 8 warps of 64x32.
// smem row = 32 words (64 bf16) + 4 pad = 36 words (conflict-free frags & stores)
// MODE: 0=PROJ->bf16(bias), 1=VPROJT->bf16(bias along m, [B,H,D,S] scatter),
//       2=WO->fp32(bias), 4=FFN1->bf16(bias+relu), 5=FFN2->fp32+bf16(bias+resid)
struct GB {
    const bf16* A; const bf16* Bm;
    const float* bias; const float* resid;
    float* Cf; bf16* Cb;
    int lda, ldb, ldc;
};

#define GSA 36

__device__ __forceinline__ void gload(uint32_t* dst, const bf16* src, int ld, int koff) {
    const int t = threadIdx.x;
    #pragma unroll
    for (int i = 0; i < 4; i++) {
        int idx = t + i * 256;
        int r = idx >> 3, c8 = idx & 7;
        cp_async16(smem_u32(dst + r * GSA + c8 * 4), src + (size_t)r * ld + koff + c8 * 8);
    }
}

template<int MODE, int NC>
__global__ __launch_bounds__(256) void gemmB(GB g) {
    extern __shared__ uint32_t smw[];
    constexpr int ASZ = 128 * GSA;
    uint32_t* A_sm[2] = { smw, smw + ASZ };
    uint32_t* B_sm[2] = { smw + 2 * ASZ, smw + 3 * ASZ };

    const int tid = threadIdx.x, w = tid >> 5, lane = tid & 31;
    const int gq = lane >> 2, q = lane & 3;
    const int wm = (w >> 2) * 64, wn = (w & 3) * 32;
    const int m0 = blockIdx.y * 128, n0 = blockIdx.x * 128;
    const bf16* Ab = g.A + (size_t)m0 * g.lda;
    const bf16* Bb = g.Bm + (size_t)n0 * g.ldb;

    float c[4][4][4];
    #pragma unroll
    for (int mt = 0; mt < 4; mt++)
        #pragma unroll
        for (int nt = 0; nt < 4; nt++)
            #pragma unroll
            for (int j = 0; j < 4; j++) c[mt][nt][j] = 0.0f;

    gload(A_sm[0], Ab, g.lda, 0);
    gload(B_sm[0], Bb, g.ldb, 0);
    cp_commit();

    #pragma unroll 1
    for (int ch = 0; ch < NC; ch++) {
        const int cur = ch & 1;
        cp_wait0();
        __syncthreads();
        if (ch + 1 < NC) {
            gload(A_sm[cur ^ 1], Ab, g.lda, (ch + 1) * 64);
            gload(B_sm[cur ^ 1], Bb, g.ldb, (ch + 1) * 64);
            cp_commit();
        }
        const uint32_t* As = A_sm[cur];
        const uint32_t* Bs = B_sm[cur];
        #pragma unroll
        for (int ks = 0; ks < 4; ks++) {
            uint32_t a[4][4], b[4][2];
            #pragma unroll
            for (int mt = 0; mt < 4; mt++) {
                int base = (wm + mt * 16 + gq) * GSA + ks * 8 + q;
                a[mt][0] = As[base];
                a[mt][1] = As[base + 8 * GSA];
                a[mt][2] = As[base + 4];
                a[mt][3] = As[base + 8 * GSA + 4];
            }
            #pragma unroll
            for (int nt = 0; nt < 4; nt++) {
                int base = (wn + nt * 8 + gq) * GSA + ks * 8 + q;
                b[nt][0] = Bs[base];
                b[nt][1] = Bs[base + 4];
            }
            #pragma unroll
            for (int mt = 0; mt < 4; mt++)
                #pragma unroll
                for (int nt = 0; nt < 4; nt++)
                    mma_bf16(c[mt][nt], a[mt], b[nt]);
        }
        __syncthreads();
    }

    // ------------- epilogue ---------------------------------------------------
    #pragma unroll
    for (int mt = 0; mt < 4; mt++) {
        #pragma unroll
        for (int nt = 0; nt < 4; nt++) {
            const int m = m0 + wm + mt * 16 + gq;
            const int n = n0 + wn + nt * 8 + 2 * q;
            float v00 = c[mt][nt][0], v01 = c[mt][nt][1];
            float v10 = c[mt][nt][2], v11 = c[mt][nt][3];
            if (MODE == 1) {
                float bm0 = g.bias[m], bm1 = g.bias[m + 8];
                v00 += bm0; v01 += bm0; v10 += bm1; v11 += bm1;
                // m = h*64+d (global d), n = b*512+s ; C[B,H,D,S]
                size_t base = ((size_t)(n >> 9) * 8 + (m >> 6)) * 32768 +
                              (size_t)(m & 63) * 512 + (n & 511);
                ((uint32_t*)g.Cb)[base >> 1]                = packbf(v00, v01);
                ((uint32_t*)g.Cb)[(base + 8 * 512) >> 1]    = packbf(v10, v11);
            } else {
                float bx = g.bias[n], by = g.bias[n + 1];
                v00 += bx; v01 += by; v10 += bx; v11 += by;
                if (MODE == 4) {
                    v00 = fmaxf(v00, 0.f); v01 = fmaxf(v01, 0.f);
                    v10 = fmaxf(v10, 0.f); v11 = fmaxf(v11, 0.f);
                }
                if (MODE == 5) {
                    const float* r0 = g.resid + (size_t)m * g.ldc + n;
                    const float* r1 = g.resid + (size_t)(m + 8) * g.ldc + n;
                    v00 += r0[0]; v01 += r0[1]; v10 += r1[0]; v11 += r1[1];
                }
                size_t e0 = (size_t)m * g.ldc + n;
                size_t e1 = (size_t)(m + 8) * g.ldc + n;
                if (MODE == 2 || MODE == 5) {
                    float2 o0 = { v00, v01 }, o1 = { v10, v11 };
                    *(float2*)(g.Cf + e0) = o0;
                    *(float2*)(g.Cf + e1) = o1;
                }
                if (MODE == 0 || MODE == 4 || MODE == 5) {
                    ((uint32_t*)g.Cb)[e0 >> 1] = packbf(v00, v01);
                    ((uint32_t*)g.Cb)[e1 >> 1] = packbf(v10, v11);
                }
            }
        }
    }
}

// ---------------- fused flash attention (bf16) --------------------------------
// grid (S_/128, BH_), 256 thr. K tiles 128x64 bf16, Vt 64x128 bf16, P 128x128 bf16.
#define FSK 36
#define FSV 68
#define FSP 68
#define FL_WORDS (2*128*FSK + 2*64*FSV + 128*FSP)   /* 26624 words */
#define FL_SMEM  (FL_WORDS * 4)                      /* 106496 B */

__global__ __launch_bounds__(256) void flashB(float scale) {
    extern __shared__ uint32_t smw[];
    uint32_t* Ks[2] = { smw, smw + 128 * FSK };
    uint32_t* Vs[2] = { smw + 2 * 128 * FSK, smw + 2 * 128 * FSK + 64 * FSV };
    uint32_t* Ps = smw + 2 * 128 * FSK + 2 * 64 * FSV;

    const int tid = threadIdx.x, w = tid >> 5, lane = tid & 31;
    const int gq = lane >> 2, q = lane & 3;
    const int z = blockIdx.y, b = z >> 3, h = z & 7;
    const int q0 = blockIdx.x * 128;

    const bf16* Qg = g_qb + ((size_t)b * S_ + q0) * E_ + h * 64;
    const bf16* Kg = g_kb + (size_t)b * S_ * E_ + h * 64;
    const bf16* Vg = g_vtb + (size_t)z * (64 * S_);

    // stage Q (128 x 64 bf16) into Ps
    #pragma unroll
    for (int i = 0; i < 4; i++) {
        int idx = tid + i * 256;
        int r = idx >> 3, c8 = idx & 7;
        cp_async16(smem_u32(Ps + r * FSP + c8 * 4), Qg + (size_t)r * E_ + c8 * 8);
    }
    cp_commit();
    // K/V tile 0
    #pragma unroll
    for (int i = 0; i < 4; i++) {
        int idx = tid + i * 256;
        int r = idx >> 3, c8 = idx & 7;
        cp_async16(smem_u32(Ks[0] + r * FSK + c8 * 4), Kg + (size_t)r * E_ + c8 * 8);
    }
    #pragma unroll
    for (int i = 0; i < 4; i++) {
        int idx = tid + i * 256;
        int r = idx >> 4, c16 = idx & 15;
        cp_async16(smem_u32(Vs[0] + r * FSV + c16 * 4), Vg + (size_t)r * S_ + c16 * 8);
    }
    cp_commit();

    cp_wait1();
    __syncthreads();

    uint32_t qf[4][4];
    {
        int base = (w * 16 + gq) * FSP + q;
        #pragma unroll
        for (int ks = 0; ks < 4; ks++) {
            qf[ks][0] = Ps[base + ks * 8];
            qf[ks][1] = Ps[base + ks * 8 + 8 * FSP];
            qf[ks][2] = Ps[base + ks * 8 + 4];
            qf[ks][3] = Ps[base + ks * 8 + 8 * FSP + 4];
        }
    }

    float o[8][4];
    #pragma unroll
    for (int i = 0; i < 8; i++)
        #pragma unroll
        for (int j = 0; j < 4; j++) o[i][j] = 0.0f;
    float mr0 = -1e30f, mr1 = -1e30f, l0 = 0.0f, l1 = 0.0f;

    #pragma unroll 1
    for (int kt = 0; kt < 4; kt++) {
        const int cur = kt & 1;
        cp_wait0();
        __syncthreads();
        if (kt < 3) {
            const int nxt = cur ^ 1;
            const bf16* Kn = Kg + (size_t)(kt + 1) * 128 * E_;
            #pragma unroll
            for (int i = 0; i < 4; i++) {
                int idx = tid + i * 256;
                int r = idx >> 3, c8 = idx & 7;
                cp_async16(smem_u32(Ks[nxt] + r * FSK + c8 * 4), Kn + (size_t)r * E_ + c8 * 8);
            }
            const bf16* Vn = Vg + (kt + 1) * 128;
            #pragma unroll
            for (int i = 0; i < 4; i++) {
                int idx = tid + i * 256;
                int r = idx >> 4, c16 = idx & 15;
                cp_async16(smem_u32(Vs[nxt] + r * FSV + c16 * 4), Vn + (size_t)r * S_ + c16 * 8);
            }
            cp_commit();
        }

        // ---- S = Q @ K^T ----
        float s[16][4];
        #pragma unroll
        for (int nf = 0; nf < 16; nf++)
            #pragma unroll
            for (int j = 0; j < 4; j++) s[nf][j] = 0.0f;
        #pragma unroll
        for (int ks = 0; ks < 4; ks++) {
            #pragma unroll
            for (int nf = 0; nf < 16; nf++) {
                int base = (nf * 8 + gq) * FSK + ks * 8 + q;
                uint32_t bb[2] = { Ks[cur][base], Ks[cur][base + 4] };
                mma_bf16(s[nf], qf[ks], bb);
            }
        }

        // ---- scale + row max ----
        float mt0 = -1e30f, mt1 = -1e30f;
        #pragma unroll
        for (int nf = 0; nf < 16; nf++) {
            s[nf][0] *= scale; s[nf][1] *= scale;
            s[nf][2] *= scale; s[nf][3] *= scale;
            mt0 = fmaxf(mt0, fmaxf(s[nf][0], s[nf][1]));
            mt1 = fmaxf(mt1, fmaxf(s[nf][2], s[nf][3]));
        }
        mt0 = fmaxf(mt0, __shfl_xor_sync(0xFFFFFFFFu, mt0, 1));
        mt0 = fmaxf(mt0, __shfl_xor_sync(0xFFFFFFFFu, mt0, 2));
        mt1 = fmaxf(mt1, __shfl_xor_sync(0xFFFFFFFFu, mt1, 1));
        mt1 = fmaxf(mt1, __shfl_xor_sync(0xFFFFFFFFu, mt1, 2));

        float mn0 = fmaxf(mr0, mt0), mn1 = fmaxf(mr1, mt1);
        float al0 = __expf(mr0 - mn0), al1 = __expf(mr1 - mn1);

        // ---- P = exp(S-m) -> bf16 pairs into Ps (warp-local rows), row sums ----
        float sum0 = 0.0f, sum1 = 0.0f;
        int prow = (w * 16 + gq) * FSP + q;
        #pragma unroll
        for (int nf = 0; nf < 16; nf++) {
            float p0 = __expf(s[nf][0] - mn0), p1 = __expf(s[nf][1] - mn0);
            float p2 = __expf(s[nf][2] - mn1), p3 = __expf(s[nf][3] - mn1);
            sum0 += p0 + p1; sum1 += p2 + p3;
            Ps[prow + nf * 4]           = packbf(p0, p1);
            Ps[prow + nf * 4 + 8 * FSP] = packbf(p2, p3);
        }
        sum0 += __shfl_xor_sync(0xFFFFFFFFu, sum0, 1);
        sum0 += __shfl_xor_sync(0xFFFFFFFFu, sum0, 2);
        sum1 += __shfl_xor_sync(0xFFFFFFFFu, sum1, 1);
        sum1 += __shfl_xor_sync(0xFFFFFFFFu, sum1, 2);
        l0 = l0 * al0 + sum0;
        l1 = l1 * al1 + sum1;
        mr0 = mn0; mr1 = mn1;

        #pragma unroll
        for (int nf2 = 0; nf2 < 8; nf2++) {
            o[nf2][0] *= al0; o[nf2][1] *= al0;
            o[nf2][2] *= al1; o[nf2][3] *= al1;
        }
        __syncwarp();

        // ---- O += P @ V ----
        #pragma unroll
        for (int ks2 = 0; ks2 < 8; ks2++) {
            int base = (w * 16 + gq) * FSP + ks2 * 8 + q;
            uint32_t aa[4] = { Ps[base], Ps[base + 8 * FSP], Ps[base + 4], Ps[base + 8 * FSP + 4] };
            #pragma unroll
            for (int nf2 = 0; nf2 < 8; nf2++) {
                int bb0 = (nf2 * 8 + gq) * FSV + ks2 * 8 + q;
                uint32_t bb[2] = { Vs[cur][bb0], Vs[cur][bb0 + 4] };
                mma_bf16(o[nf2], aa, bb);
            }
        }
        __syncwarp();
    }

    // ---- epilogue: O / l -> g_catb[b, s, h*64+d] (bf16) ----
    float li0 = 1.0f / l0, li1 = 1.0f / l1;
    const int m = q0 + w * 16 + gq;
    size_t base0 = ((size_t)b * S_ + m) * E_ + h * 64 + 2 * q;
    size_t base1 = base0 + (size_t)8 * E_;
    #pragma unroll
    for (int nf2 = 0; nf2 < 8; nf2++) {
        ((uint32_t*)g_catb)[(base0 + nf2 * 8) >> 1] = packbf(o[nf2][0] * li0, o[nf2][1] * li0);
        ((uint32_t*)g_catb)[(base1 + nf2 * 8) >> 1] = packbf(o[nf2][2] * li1, o[nf2][3] * li1);
    }
}

// ---------------- weight transpose+convert: src [K,N] fp32 -> dst [N,K] bf16 --
__global__ void transpose_kernel(const float* __restrict__ src, bf16* __restrict__ dst,
                                 int K, int N) {
    __shared__ float t[32][33];
    int z = blockIdx.z;
    src += (size_t)z * K * N;
    dst += (size_t)z * N * K;
    int n0 = blockIdx.x * 32, k0 = blockIdx.y * 32;
    for (int i = threadIdx.y; i < 32; i += 8)
        t[i][threadIdx.x] = src[(size_t)(k0 + i) * N + n0 + threadIdx.x];
    __syncthreads();
    for (int i = threadIdx.y; i < 32; i += 8)
        dst[(size_t)(n0 + i) * K + k0 + threadIdx.x] = __float2bfloat16(t[threadIdx.x][i]);
}

// ---------------- embedding gather + mask (fp32 + bf16) -----------------------
__global__ void embed_kernel(const int* __restrict__ tokens, const float* __restrict__ emb) {
    int gid = blockIdx.x * 256 + threadIdx.x;   // over M*E/4
    int idx = gid * 4;
    int m = idx >> 9;
    int e = idx & 511;
    int t = tokens[m];
    float4 v = { 0.f, 0.f, 0.f, 0.f };
    if (t > 0) v = *(const float4*)(emb + (size_t)t * E_ + e);
    *(float4*)(g_out + idx) = v;
    uint2 hb = { packbf(v.x, v.y), packbf(v.z, v.w) };
    ((uint2*)g_outb)[gid] = hb;
}

// ---------------- residual add + l2 normalize (128 thr, float4) ---------------
__global__ void addnorm_kernel() {
    int row = blockIdx.x;
    float4* o4 = (float4*)(g_out + (size_t)row * E_);
    const float4* m4 = (const float4*)(g_mh + (size_t)row * E_);
    int t = threadIdx.x;
    float4 a = o4[t], m = m4[t];
    a.x += m.x; a.y += m.y; a.z += m.z; a.w += m.w;
    float sq = a.x * a.x + a.y * a.y + a.z * a.z + a.w * a.w;
    #pragma unroll
    for (int o = 16; o; o >>= 1) sq += __shfl_xor_sync(0xFFFFFFFFu, sq, o);
    __shared__ float red[4];
    if ((t & 31) == 0) red[t >> 5] = sq;
    __syncthreads();
    float inv = rsqrtf(fmaxf(red[0] + red[1] + red[2] + red[3], 1e-12f));
    a.x *= inv; a.y *= inv; a.z *= inv; a.w *= inv;
    o4[t] = a;
    uint2 hb = { packbf(a.x, a.y), packbf(a.z, a.w) };
    ((uint2*)g_outb)[(size_t)row * 128 + t] = hb;
}

// ---------------- conv1d(KW=5, stride=5) -------------------------------------
__global__ void conv_kernel(const float* __restrict__ Wc, const float* __restrict__ bc) {
    int b = blockIdx.x / LOUT_;
    int j = blockIdx.x % LOUT_;
    const float* base = g_out + ((size_t)b * S_ + j * STRIDE_) * E_;
    float acc = 0.0f;
    for (int i = threadIdx.x; i < KW_ * E_; i += 256)
        acc += base[i] * Wc[i];
    __shared__ float red[256];
    red[threadIdx.x] = acc;
    __syncthreads();
    for (int s = 128; s > 0; s >>= 1) {
        if (threadIdx.x < s) red[threadIdx.x] += red[threadIdx.x + s];
        __syncthreads();
    }
    if (threadIdx.x == 0) g_pooled[b * LOUT_ + j] = red[0] + bc[0];
}

// ---------------- final dense + softmax over 1000 ----------------------------
__global__ void dense_softmax_kernel(const float* __restrict__ Wd,
                                     const float* __restrict__ bd,
                                     float* __restrict__ outp) {
    int b = blockIdx.x;
    __shared__ float p[LOUT_];
    int t = threadIdx.x;
    if (t < LOUT_) p[t] = g_pooled[b * LOUT_ + t];
    __syncthreads();

    float lg[4];
    #pragma unroll
    for (int u = 0; u < 4; u++) {
        int o = t + u * 256;
        float acc = -1e30f;
        if (o < O_) {
            acc = bd[o];
            for (int j = 0; j < LOUT_; j++)
                acc += p[j] * Wd[j * O_ + o];
        }
        lg[u] = acc;
    }
    __shared__ float red[256];
    float m = fmaxf(fmaxf(lg[0], lg[1]), fmaxf(lg[2], lg[3]));
    red[t] = m;
    __syncthreads();
    for (int s = 128; s > 0; s >>= 1) {
        if (t < s) red[t] = fmaxf(red[t], red[t + s]);
        __syncthreads();
    }
    float mx = red[0];
    __syncthreads();
    float e[4], sum = 0.0f;
    #pragma unroll
    for (int u = 0; u < 4; u++) {
        e[u] = expf(lg[u] - mx);
        sum += e[u];
    }
    red[t] = sum;
    __syncthreads();
    for (int s = 128; s > 0; s >>= 1) {
        if (t < s) red[t] += red[t + s];
        __syncthreads();
    }
    float inv = 1.0f / red[0];
    #pragma unroll
    for (int u = 0; u < 4; u++) {
        int o = t + u * 256;
        if (o < O_) outp[(size_t)b * O_ + o] = e[u] * inv;
    }
}

// ---------------- host launcher ----------------------------------------------
static const int SMEM_G = 4 * 128 * GSA * 4;   // 73728 B

extern "C" void kernel_launch(void* const* d_in, const int* in_sizes, int n_in,
                              void* d_out, int out_size) {
    const int*   tokens = (const int*)  d_in[0];
    const float* emb    = (const float*)d_in[1];
    const float* Wq     = (const float*)d_in[2];
    const float* bq     = (const float*)d_in[3];
    const float* Wk     = (const float*)d_in[4];
    const float* bk     = (const float*)d_in[5];
    const float* Wv     = (const float*)d_in[6];
    const float* bv     = (const float*)d_in[7];
    const float* Wo     = (const float*)d_in[8];
    const float* bo     = (const float*)d_in[9];
    const float* W1     = (const float*)d_in[10];
    const float* b1     = (const float*)d_in[11];
    const float* W2     = (const float*)d_in[12];
    const float* b2     = (const float*)d_in[13];
    const float* Wc     = (const float*)d_in[14];
    const float* bc     = (const float*)d_in[15];
    const float* Wd     = (const float*)d_in[16];
    const float* bd     = (const float*)d_in[17];
    float* outp = (float*)d_out;
    (void)in_sizes; (void)n_in; (void)out_size;

    float *p_out, *p_mh;
    bf16 *p_outb, *p_qb, *p_kb, *p_vtb, *p_catb, *p_ffb, *p_wtb;
    cudaGetSymbolAddress((void**)&p_out,  g_out);
    cudaGetSymbolAddress((void**)&p_mh,   g_mh);
    cudaGetSymbolAddress((void**)&p_outb, g_outb);
    cudaGetSymbolAddress((void**)&p_qb,   g_qb);
    cudaGetSymbolAddress((void**)&p_kb,   g_kb);
    cudaGetSymbolAddress((void**)&p_vtb,  g_vtb);
    cudaGetSymbolAddress((void**)&p_catb, g_catb);
    cudaGetSymbolAddress((void**)&p_ffb,  g_ffb);
    cudaGetSymbolAddress((void**)&p_wtb,  g_wtb);

    cudaFuncSetAttribute(gemmB<0,8>,  cudaFuncAttributeMaxDynamicSharedMemorySize, SMEM_G);
    cudaFuncSetAttribute(gemmB<1,8>,  cudaFuncAttributeMaxDynamicSharedMemorySize, SMEM_G);
    cudaFuncSetAttribute(gemmB<2,8>,  cudaFuncAttributeMaxDynamicSharedMemorySize, SMEM_G);
    cudaFuncSetAttribute(gemmB<4,8>,  cudaFuncAttributeMaxDynamicSharedMemorySize, SMEM_G);
    cudaFuncSetAttribute(gemmB<5,16>, cudaFuncAttributeMaxDynamicSharedMemorySize, SMEM_G);
    cudaFuncSetAttribute(flashB,      cudaFuncAttributeMaxDynamicSharedMemorySize, FL_SMEM);

    const float scale = 0.044194173824159216f;  // 1/sqrt(512)
    dim3 tthr(32, 8);

    // ---- pre-transpose+convert all weights to bf16 [N,K] ----
    for (int i = 0; i < L_; i++) {
        bf16* wt = p_wtb + (size_t)i * LWT_;
        transpose_kernel<<<dim3(2, 16, 8), tthr>>>(Wq + (size_t)i*H_*E_*D_, wt + QT_,  512, 64);
        transpose_kernel<<<dim3(2, 16, 8), tthr>>>(Wk + (size_t)i*H_*E_*D_, wt + KT_,  512, 64);
        transpose_kernel<<<dim3(2, 16, 8), tthr>>>(Wv + (size_t)i*H_*E_*D_, wt + VTW_, 512, 64);
        transpose_kernel<<<dim3(16, 16, 1), tthr>>>(Wo + (size_t)i*E_*E_,   wt + OT_,  512, 512);
        transpose_kernel<<<dim3(32, 16, 1), tthr>>>(W1 + (size_t)i*E_*2*E_, wt + W1T_, 512, 1024);
        transpose_kernel<<<dim3(16, 32, 1), tthr>>>(W2 + (size_t)i*2*E_*E_, wt + W2T_, 1024, 512);
    }

    embed_kernel<<<(M_ * E_) / 1024, 256>>>(tokens, emb);

    for (int i = 0; i < L_; i++) {
        bf16* wt = p_wtb + (size_t)i * LWT_;
        GB a;

        // Q = out @ Wq^T + bq  -> bf16 [B,S,H*D]
        a = { p_outb, wt + QT_, bq + (size_t)i*512, nullptr, nullptr, p_qb, 512, 512, 512 };
        gemmB<0,8><<<dim3(4, 256), 256, SMEM_G>>>(a);
        // K
        a = { p_outb, wt + KT_, bk + (size_t)i*512, nullptr, nullptr, p_kb, 512, 512, 512 };
        gemmB<0,8><<<dim3(4, 256), 256, SMEM_G>>>(a);
        // V^T = Wv^T @ out^T + bv  -> bf16 [B,H,D,S]  (A=weights, B=activations)
        a = { wt + VTW_, p_outb, bv + (size_t)i*512, nullptr, nullptr, p_vtb, 512, 512, 0 };
        gemmB<1,8><<<dim3(256, 4), 256, SMEM_G>>>(a);

        // fused attention -> g_catb (bf16)
        flashB<<<dim3(S_/128, BH_), 256, FL_SMEM>>>(scale);

        // mh = cat @ Wo^T + bo  -> fp32
        a = { p_catb, wt + OT_, bo + (size_t)i*512, nullptr, p_mh, nullptr, 512, 512, 512 };
        gemmB<2,8><<<dim3(4, 256), 256, SMEM_G>>>(a);

        addnorm_kernel<<<M_, 128>>>();

        // ff = relu(out @ W1^T + b1)  -> bf16
        a = { p_outb, wt + W1T_, b1 + (size_t)i*1024, nullptr, nullptr, p_ffb, 512, 512, 1024 };
        gemmB<4,8><<<dim3(8, 256), 256, SMEM_G>>>(a);

        // out = ff @ W2^T + b2 + out  -> fp32 + bf16
        a = { p_ffb, wt + W2T_, b2 + (size_t)i*512, p_out, p_out, p_outb, 1024, 1024, 512 };
        gemmB<5,16><<<dim3(4, 256), 256, SMEM_G>>>(a);
    }

    conv_kernel<<<B_ * LOUT_, 256>>>(Wc, bc);
    dense_softmax_kernel<<<B_, 256>>>(Wd, bd, outp);
}

// round 8
// speedup vs baseline: 8.1496x; 1.1305x over previous
#include <cuda_runtime.h>
#include <cuda_bf16.h>
#include <cstdint>
#include <math.h>

#define B_ 64
#define S_ 512
#define E_ 512
#define H_ 8
#define D_ 64
#define L_ 4
#define O_ 1000
#define KW_ 5
#define STRIDE_ 5
#define LOUT_ 102
#define BH_ (B_*H_)
#define M_ (B_*S_)   /* 32768 */

typedef __nv_bfloat16 bf16;

// ---------------- scratch ----------------------------------------------------
__device__ float g_out[M_*E_];              // fp32 master activations [B,S,E]
__device__ float g_mh[M_*E_];               // attention block output (fp32)
__device__ float g_pooled[B_*LOUT_];
__device__ bf16  g_outb[M_*E_];             // bf16 shadow of g_out
__device__ bf16  g_qb[M_*E_];               // [B,S,H*D]
__device__ bf16  g_kb[M_*E_];               // [B,S,H*D]
__device__ bf16  g_vtb[M_*E_];              // [B,H,D,S]
__device__ bf16  g_catb[M_*E_];             // [B,S,H*D]
__device__ bf16  g_ffb[M_*2*E_];            // FFN hidden
#define LWT_ 2097152
__device__ bf16  g_wtb[(size_t)L_*LWT_];    // transposed bf16 weights per layer
#define QT_  0
#define KT_  262144
#define VTW_ 524288
#define OT_  786432
#define W1T_ 1048576
#define W2T_ 1572864

// ---------------- helpers -----------------------------------------------------
__device__ __forceinline__ uint32_t smem_u32(const void* p) {
    uint32_t a;
    asm("{ .reg .u64 t; cvta.to.shared.u64 t, %1; cvt.u32.u64 %0, t; }" : "=r"(a) : "l"(p));
    return a;
}
__device__ __forceinline__ void cp_async16(uint32_t dst, const void* src) {
    asm volatile("cp.async.cg.shared.global [%0], [%1], 16;" :: "r"(dst), "l"(src) : "memory");
}
__device__ __forceinline__ void cp_commit() {
    asm volatile("cp.async.commit_group;" ::: "memory");
}
__device__ __forceinline__ void cp_wait0() {
    asm volatile("cp.async.wait_group 0;" ::: "memory");
}
__device__ __forceinline__ void cp_wait1() {
    asm volatile("cp.async.wait_group 1;" ::: "memory");
}
__device__ __forceinline__ void mma_bf16(float* c, const uint32_t* a, const uint32_t* b) {
    asm volatile(
        "mma.sync.aligned.m16n8k16.row.col.f32.bf16.bf16.f32 "
        "{%0,%1,%2,%3}, {%4,%5,%6,%7}, {%8,%9}, {%0,%1,%2,%3};"
        : "+f"(c[0]), "+f"(c[1]), "+f"(c[2]), "+f"(c[3])
        : "r"(a[0]), "r"(a[1]), "r"(a[2]), "r"(a[3]), "r"(b[0]), "r"(b[1]));
}
__device__ __forceinline__ void ldsm4(uint32_t* r, uint32_t addr) {
    asm volatile("ldmatrix.sync.aligned.m8n8.x4.shared.b16 {%0,%1,%2,%3}, [%4];"
        : "=r"(r[0]), "=r"(r[1]), "=r"(r[2]), "=r"(r[3]) : "r"(addr));
}
__device__ __forceinline__ uint32_t packbf(float a, float b) {
    __nv_bfloat162 h = __floats2bfloat162_rn(a, b);
    return *(uint32_t*)&h;
}

// ---------------- bf16 mma GEMM ----------------------------------------------
// CTA tile 128x128, k-chunk 64 (bf16), 8 warps of 64x32, ldmatrix fragment loads.
// MODE: 0=PROJ->bf16(bias), 1=VPROJT->bf16(bias along m, [B,H,D,S] scatter),
//       2=WO->fp32(bias), 4=FFN1->bf16(bias+relu), 5=FFN2->fp32+bf16(bias+resid)
struct GB {
    const bf16* A; const bf16* Bm;
    const float* bias; const float* resid;
    float* Cf; bf16* Cb;
    int lda, ldb, ldc;
};

#define GSA 36

__device__ __forceinline__ void gload(uint32_t* dst, const bf16* src, int ld, int koff) {
    const int t = threadIdx.x;
    #pragma unroll
    for (int i = 0; i < 4; i++) {
        int idx = t + i * 256;
        int r = idx >> 3, c8 = idx & 7;
        cp_async16(smem_u32(dst + r * GSA + c8 * 4), src + (size_t)r * ld + koff + c8 * 8);
    }
}

template<int MODE, int NC>
__global__ __launch_bounds__(256, 2) void gemmB(GB g) {
    extern __shared__ uint32_t smw[];
    constexpr int ASZ = 128 * GSA;
    uint32_t* A_sm[2] = { smw, smw + ASZ };
    uint32_t* B_sm[2] = { smw + 2 * ASZ, smw + 3 * ASZ };
    const uint32_t SB = smem_u32(smw);

    const int tid = threadIdx.x, w = tid >> 5, lane = tid & 31;
    const int gq = lane >> 2, q = lane & 3;
    const int lr = lane & 15, lc = (lane >> 4) * 4;   // ldmatrix row / word-chunk
    const int wm = (w >> 2) * 64, wn = (w & 3) * 32;
    const int m0 = blockIdx.y * 128, n0 = blockIdx.x * 128;
    const bf16* Ab = g.A + (size_t)m0 * g.lda;
    const bf16* Bb = g.Bm + (size_t)n0 * g.ldb;

    const uint32_t aOff = ((wm + lr) * GSA + lc) * 4;
    const uint32_t bOff = ((wn + lr) * GSA + lc) * 4;

    float c[4][4][4];
    #pragma unroll
    for (int mt = 0; mt < 4; mt++)
        #pragma unroll
        for (int nt = 0; nt < 4; nt++)
            #pragma unroll
            for (int j = 0; j < 4; j++) c[mt][nt][j] = 0.0f;

    gload(A_sm[0], Ab, g.lda, 0);
    gload(B_sm[0], Bb, g.ldb, 0);
    cp_commit();

    #pragma unroll 1
    for (int ch = 0; ch < NC; ch++) {
        const int cur = ch & 1;
        cp_wait0();
        __syncthreads();
        if (ch + 1 < NC) {
            gload(A_sm[cur ^ 1], Ab, g.lda, (ch + 1) * 64);
            gload(B_sm[cur ^ 1], Bb, g.ldb, (ch + 1) * 64);
            cp_commit();
        }
        const uint32_t Ab_s = SB + cur * (ASZ * 4) + aOff;
        const uint32_t Bb_s = SB + (2 + cur) * (ASZ * 4) + bOff;
        #pragma unroll
        for (int ks = 0; ks < 4; ks++) {
            uint32_t a[4][4], b[2][4];
            #pragma unroll
            for (int mt = 0; mt < 4; mt++)
                ldsm4(a[mt], Ab_s + mt * (16 * GSA * 4) + ks * 32);
            #pragma unroll
            for (int nt2 = 0; nt2 < 2; nt2++)
                ldsm4(b[nt2], Bb_s + nt2 * (16 * GSA * 4) + ks * 32);
            #pragma unroll
            for (int mt = 0; mt < 4; mt++) {
                #pragma unroll
                for (int nt2 = 0; nt2 < 2; nt2++) {
                    uint32_t b0[2] = { b[nt2][0], b[nt2][2] };
                    uint32_t b1[2] = { b[nt2][1], b[nt2][3] };
                    mma_bf16(c[mt][nt2 * 2],     a[mt], b0);
                    mma_bf16(c[mt][nt2 * 2 + 1], a[mt], b1);
                }
            }
        }
        __syncthreads();
    }

    // ------------- epilogue ---------------------------------------------------
    #pragma unroll
    for (int mt = 0; mt < 4; mt++) {
        #pragma unroll
        for (int nt = 0; nt < 4; nt++) {
            const int m = m0 + wm + mt * 16 + gq;
            const int n = n0 + wn + nt * 8 + 2 * q;
            float v00 = c[mt][nt][0], v01 = c[mt][nt][1];
            float v10 = c[mt][nt][2], v11 = c[mt][nt][3];
            if (MODE == 1) {
                float bm0 = g.bias[m], bm1 = g.bias[m + 8];
                v00 += bm0; v01 += bm0; v10 += bm1; v11 += bm1;
                // m = h*64+d (global d), n = b*512+s ; C[B,H,D,S]
                size_t base = ((size_t)(n >> 9) * 8 + (m >> 6)) * 32768 +
                              (size_t)(m & 63) * 512 + (n & 511);
                ((uint32_t*)g.Cb)[base >> 1]                = packbf(v00, v01);
                ((uint32_t*)g.Cb)[(base + 8 * 512) >> 1]    = packbf(v10, v11);
            } else {
                float bx = g.bias[n], by = g.bias[n + 1];
                v00 += bx; v01 += by; v10 += bx; v11 += by;
                if (MODE == 4) {
                    v00 = fmaxf(v00, 0.f); v01 = fmaxf(v01, 0.f);
                    v10 = fmaxf(v10, 0.f); v11 = fmaxf(v11, 0.f);
                }
                if (MODE == 5) {
                    const float* r0 = g.resid + (size_t)m * g.ldc + n;
                    const float* r1 = g.resid + (size_t)(m + 8) * g.ldc + n;
                    v00 += r0[0]; v01 += r0[1]; v10 += r1[0]; v11 += r1[1];
                }
                size_t e0 = (size_t)m * g.ldc + n;
                size_t e1 = (size_t)(m + 8) * g.ldc + n;
                if (MODE == 2 || MODE == 5) {
                    float2 o0 = { v00, v01 }, o1 = { v10, v11 };
                    *(float2*)(g.Cf + e0) = o0;
                    *(float2*)(g.Cf + e1) = o1;
                }
                if (MODE == 0 || MODE == 4 || MODE == 5) {
                    ((uint32_t*)g.Cb)[e0 >> 1] = packbf(v00, v01);
                    ((uint32_t*)g.Cb)[e1 >> 1] = packbf(v10, v11);
                }
            }
        }
    }
}

// ---------------- fused flash attention (bf16 + ldmatrix) ---------------------
// grid (S_/128, BH_), 256 thr. K tiles 128x64 bf16, Vt 64x128 bf16, P 128x128 bf16.
#define FSK 36
#define FSV 68
#define FSP 68
#define FL_WORDS (2*128*FSK + 2*64*FSV + 128*FSP)   /* 26624 words */
#define FL_SMEM  (FL_WORDS * 4)                      /* 106496 B */

__global__ __launch_bounds__(256) void flashB(float scale) {
    extern __shared__ uint32_t smw[];
    uint32_t* Ks[2] = { smw, smw + 128 * FSK };
    uint32_t* Vs[2] = { smw + 2 * 128 * FSK, smw + 2 * 128 * FSK + 64 * FSV };
    uint32_t* Ps = smw + 2 * 128 * FSK + 2 * 64 * FSV;
    const uint32_t PsB = smem_u32(Ps);

    const int tid = threadIdx.x, w = tid >> 5, lane = tid & 31;
    const int gq = lane >> 2, q = lane & 3;
    const int lr = lane & 15, lc = (lane >> 4) * 4;
    const int z = blockIdx.y, b = z >> 3, h = z & 7;
    const int q0 = blockIdx.x * 128;

    const bf16* Qg = g_qb + ((size_t)b * S_ + q0) * E_ + h * 64;
    const bf16* Kg = g_kb + (size_t)b * S_ * E_ + h * 64;
    const bf16* Vg = g_vtb + (size_t)z * (64 * S_);

    // stage Q (128 x 64 bf16) into Ps
    #pragma unroll
    for (int i = 0; i < 4; i++) {
        int idx = tid + i * 256;
        int r = idx >> 3, c8 = idx & 7;
        cp_async16(smem_u32(Ps + r * FSP + c8 * 4), Qg + (size_t)r * E_ + c8 * 8);
    }
    cp_commit();
    // K/V tile 0
    #pragma unroll
    for (int i = 0; i < 4; i++) {
        int idx = tid + i * 256;
        int r = idx >> 3, c8 = idx & 7;
        cp_async16(smem_u32(Ks[0] + r * FSK + c8 * 4), Kg + (size_t)r * E_ + c8 * 8);
    }
    #pragma unroll
    for (int i = 0; i < 4; i++) {
        int idx = tid + i * 256;
        int r = idx >> 4, c16 = idx & 15;
        cp_async16(smem_u32(Vs[0] + r * FSV + c16 * 4), Vg + (size_t)r * S_ + c16 * 8);
    }
    cp_commit();

    cp_wait1();
    __syncthreads();

    uint32_t qf[4][4];
    {
        uint32_t base = PsB + ((w * 16 + lr) * FSP + lc) * 4;
        #pragma unroll
        for (int ks = 0; ks < 4; ks++) ldsm4(qf[ks], base + ks * 32);
    }

    float o[8][4];
    #pragma unroll
    for (int i = 0; i < 8; i++)
        #pragma unroll
        for (int j = 0; j < 4; j++) o[i][j] = 0.0f;
    float mr0 = -1e30f, mr1 = -1e30f, l0 = 0.0f, l1 = 0.0f;

    #pragma unroll 1
    for (int kt = 0; kt < 4; kt++) {
        const int cur = kt & 1;
        cp_wait0();
        __syncthreads();
        if (kt < 3) {
            const int nxt = cur ^ 1;
            const bf16* Kn = Kg + (size_t)(kt + 1) * 128 * E_;
            #pragma unroll
            for (int i = 0; i < 4; i++) {
                int idx = tid + i * 256;
                int r = idx >> 3, c8 = idx & 7;
                cp_async16(smem_u32(Ks[nxt] + r * FSK + c8 * 4), Kn + (size_t)r * E_ + c8 * 8);
            }
            const bf16* Vn = Vg + (kt + 1) * 128;
            #pragma unroll
            for (int i = 0; i < 4; i++) {
                int idx = tid + i * 256;
                int r = idx >> 4, c16 = idx & 15;
                cp_async16(smem_u32(Vs[nxt] + r * FSV + c16 * 4), Vn + (size_t)r * S_ + c16 * 8);
            }
            cp_commit();
        }

        // ---- S = Q @ K^T ----
        const uint32_t KsB = smem_u32(Ks[cur]) + (lr * FSK + lc) * 4;
        float s[16][4];
        #pragma unroll
        for (int nf = 0; nf < 16; nf++)
            #pragma unroll
            for (int j = 0; j < 4; j++) s[nf][j] = 0.0f;
        #pragma unroll
        for (int ks = 0; ks < 4; ks++) {
            #pragma unroll
            for (int nf2 = 0; nf2 < 8; nf2++) {
                uint32_t bm[4];
                ldsm4(bm, KsB + nf2 * (16 * FSK * 4) + ks * 32);
                uint32_t b0[2] = { bm[0], bm[2] };
                uint32_t b1[2] = { bm[1], bm[3] };
                mma_bf16(s[nf2 * 2],     qf[ks], b0);
                mma_bf16(s[nf2 * 2 + 1], qf[ks], b1);
            }
        }

        // ---- scale + row max ----
        float mt0 = -1e30f, mt1 = -1e30f;
        #pragma unroll
        for (int nf = 0; nf < 16; nf++) {
            s[nf][0] *= scale; s[nf][1] *= scale;
            s[nf][2] *= scale; s[nf][3] *= scale;
            mt0 = fmaxf(mt0, fmaxf(s[nf][0], s[nf][1]));
            mt1 = fmaxf(mt1, fmaxf(s[nf][2], s[nf][3]));
        }
        mt0 = fmaxf(mt0, __shfl_xor_sync(0xFFFFFFFFu, mt0, 1));
        mt0 = fmaxf(mt0, __shfl_xor_sync(0xFFFFFFFFu, mt0, 2));
        mt1 = fmaxf(mt1, __shfl_xor_sync(0xFFFFFFFFu, mt1, 1));
        mt1 = fmaxf(mt1, __shfl_xor_sync(0xFFFFFFFFu, mt1, 2));

        float mn0 = fmaxf(mr0, mt0), mn1 = fmaxf(mr1, mt1);
        float al0 = __expf(mr0 - mn0), al1 = __expf(mr1 - mn1);

        // ---- P = exp(S-m) -> bf16 pairs into Ps (warp-local rows), row sums ----
        float sum0 = 0.0f, sum1 = 0.0f;
        int prow = (w * 16 + gq) * FSP + q;
        #pragma unroll
        for (int nf = 0; nf < 16; nf++) {
            float p0 = __expf(s[nf][0] - mn0), p1 = __expf(s[nf][1] - mn0);
            float p2 = __expf(s[nf][2] - mn1), p3 = __expf(s[nf][3] - mn1);
            sum0 += p0 + p1; sum1 += p2 + p3;
            Ps[prow + nf * 4]           = packbf(p0, p1);
            Ps[prow + nf * 4 + 8 * FSP] = packbf(p2, p3);
        }
        sum0 += __shfl_xor_sync(0xFFFFFFFFu, sum0, 1);
        sum0 += __shfl_xor_sync(0xFFFFFFFFu, sum0, 2);
        sum1 += __shfl_xor_sync(0xFFFFFFFFu, sum1, 1);
        sum1 += __shfl_xor_sync(0xFFFFFFFFu, sum1, 2);
        l0 = l0 * al0 + sum0;
        l1 = l1 * al1 + sum1;
        mr0 = mn0; mr1 = mn1;

        #pragma unroll
        for (int nf2 = 0; nf2 < 8; nf2++) {
            o[nf2][0] *= al0; o[nf2][1] *= al0;
            o[nf2][2] *= al1; o[nf2][3] *= al1;
        }
        __syncwarp();

        // ---- O += P @ V ----
        const uint32_t PsA = PsB + ((w * 16 + lr) * FSP + lc) * 4;
        const uint32_t VsB = smem_u32(Vs[cur]) + (lr * FSV + lc) * 4;
        #pragma unroll
        for (int ks2 = 0; ks2 < 8; ks2++) {
            uint32_t aa[4];
            ldsm4(aa, PsA + ks2 * 32);
            #pragma unroll
            for (int nf4 = 0; nf4 < 4; nf4++) {
                uint32_t bm[4];
                ldsm4(bm, VsB + nf4 * (16 * FSV * 4) + ks2 * 32);
                uint32_t b0[2] = { bm[0], bm[2] };
                uint32_t b1[2] = { bm[1], bm[3] };
                mma_bf16(o[nf4 * 2],     aa, b0);
                mma_bf16(o[nf4 * 2 + 1], aa, b1);
            }
        }
        __syncwarp();
    }

    // ---- epilogue: O / l -> g_catb[b, s, h*64+d] (bf16) ----
    float li0 = 1.0f / l0, li1 = 1.0f / l1;
    const int m = q0 + w * 16 + gq;
    size_t base0 = ((size_t)b * S_ + m) * E_ + h * 64 + 2 * q;
    size_t base1 = base0 + (size_t)8 * E_;
    #pragma unroll
    for (int nf2 = 0; nf2 < 8; nf2++) {
        ((uint32_t*)g_catb)[(base0 + nf2 * 8) >> 1] = packbf(o[nf2][0] * li0, o[nf2][1] * li0);
        ((uint32_t*)g_catb)[(base1 + nf2 * 8) >> 1] = packbf(o[nf2][2] * li1, o[nf2][3] * li1);
    }
}

// ---------------- weight transpose+convert: src [K,N] fp32 -> dst [N,K] bf16 --
__global__ void transpose_kernel(const float* __restrict__ src, bf16* __restrict__ dst,
                                 int K, int N) {
    __shared__ float t[32][33];
    int z = blockIdx.z;
    src += (size_t)z * K * N;
    dst += (size_t)z * N * K;
    int n0 = blockIdx.x * 32, k0 = blockIdx.y * 32;
    for (int i = threadIdx.y; i < 32; i += 8)
        t[i][threadIdx.x] = src[(size_t)(k0 + i) * N + n0 + threadIdx.x];
    __syncthreads();
    for (int i = threadIdx.y; i < 32; i += 8)
        dst[(size_t)(n0 + i) * K + k0 + threadIdx.x] = __float2bfloat16(t[threadIdx.x][i]);
}

// ---------------- embedding gather + mask (fp32 + bf16) -----------------------
__global__ void embed_kernel(const int* __restrict__ tokens, const float* __restrict__ emb) {
    int gid = blockIdx.x * 256 + threadIdx.x;   // over M*E/4
    int idx = gid * 4;
    int m = idx >> 9;
    int e = idx & 511;
    int t = tokens[m];
    float4 v = { 0.f, 0.f, 0.f, 0.f };
    if (t > 0) v = *(const float4*)(emb + (size_t)t * E_ + e);
    *(float4*)(g_out + idx) = v;
    uint2 hb = { packbf(v.x, v.y), packbf(v.z, v.w) };
    ((uint2*)g_outb)[gid] = hb;
}

// ---------------- residual add + l2 normalize (128 thr, float4) ---------------
__global__ void addnorm_kernel() {
    int row = blockIdx.x;
    float4* o4 = (float4*)(g_out + (size_t)row * E_);
    const float4* m4 = (const float4*)(g_mh + (size_t)row * E_);
    int t = threadIdx.x;
    float4 a = o4[t], m = m4[t];
    a.x += m.x; a.y += m.y; a.z += m.z; a.w += m.w;
    float sq = a.x * a.x + a.y * a.y + a.z * a.z + a.w * a.w;
    #pragma unroll
    for (int o = 16; o; o >>= 1) sq += __shfl_xor_sync(0xFFFFFFFFu, sq, o);
    __shared__ float red[4];
    if ((t & 31) == 0) red[t >> 5] = sq;
    __syncthreads();
    float inv = rsqrtf(fmaxf(red[0] + red[1] + red[2] + red[3], 1e-12f));
    a.x *= inv; a.y *= inv; a.z *= inv; a.w *= inv;
    o4[t] = a;
    uint2 hb = { packbf(a.x, a.y), packbf(a.z, a.w) };
    ((uint2*)g_outb)[(size_t)row * 128 + t] = hb;
}

// ---------------- conv1d(KW=5, stride=5) -------------------------------------
__global__ void conv_kernel(const float* __restrict__ Wc, const float* __restrict__ bc) {
    int b = blockIdx.x / LOUT_;
    int j = blockIdx.x % LOUT_;
    const float* base = g_out + ((size_t)b * S_ + j * STRIDE_) * E_;
    float acc = 0.0f;
    for (int i = threadIdx.x; i < KW_ * E_; i += 256)
        acc += base[i] * Wc[i];
    __shared__ float red[256];
    red[threadIdx.x] = acc;
    __syncthreads();
    for (int s = 128; s > 0; s >>= 1) {
        if (threadIdx.x < s) red[threadIdx.x] += red[threadIdx.x + s];
        __syncthreads();
    }
    if (threadIdx.x == 0) g_pooled[b * LOUT_ + j] = red[0] + bc[0];
}

// ---------------- final dense + softmax over 1000 ----------------------------
__global__ void dense_softmax_kernel(const float* __restrict__ Wd,
                                     const float* __restrict__ bd,
                                     float* __restrict__ outp) {
    int b = blockIdx.x;
    __shared__ float p[LOUT_];
    int t = threadIdx.x;
    if (t < LOUT_) p[t] = g_pooled[b * LOUT_ + t];
    __syncthreads();

    float lg[4];
    #pragma unroll
    for (int u = 0; u < 4; u++) {
        int o = t + u * 256;
        float acc = -1e30f;
        if (o < O_) {
            acc = bd[o];
            for (int j = 0; j < LOUT_; j++)
                acc += p[j] * Wd[j * O_ + o];
        }
        lg[u] = acc;
    }
    __shared__ float red[256];
    float m = fmaxf(fmaxf(lg[0], lg[1]), fmaxf(lg[2], lg[3]));
    red[t] = m;
    __syncthreads();
    for (int s = 128; s > 0; s >>= 1) {
        if (t < s) red[t] = fmaxf(red[t], red[t + s]);
        __syncthreads();
    }
    float mx = red[0];
    __syncthreads();
    float e[4], sum = 0.0f;
    #pragma unroll
    for (int u = 0; u < 4; u++) {
        e[u] = expf(lg[u] - mx);
        sum += e[u];
    }
    red[t] = sum;
    __syncthreads();
    for (int s = 128; s > 0; s >>= 1) {
        if (t < s) red[t] += red[t + s];
        __syncthreads();
    }
    float inv = 1.0f / red[0];
    #pragma unroll
    for (int u = 0; u < 4; u++) {
        int o = t + u * 256;
        if (o < O_) outp[(size_t)b * O_ + o] = e[u] * inv;
    }
}

// ---------------- host launcher ----------------------------------------------
static const int SMEM_G = 4 * 128 * GSA * 4;   // 73728 B

extern "C" void kernel_launch(void* const* d_in, const int* in_sizes, int n_in,
                              void* d_out, int out_size) {
    const int*   tokens = (const int*)  d_in[0];
    const float* emb    = (const float*)d_in[1];
    const float* Wq     = (const float*)d_in[2];
    const float* bq     = (const float*)d_in[3];
    const float* Wk     = (const float*)d_in[4];
    const float* bk     = (const float*)d_in[5];
    const float* Wv     = (const float*)d_in[6];
    const float* bv     = (const float*)d_in[7];
    const float* Wo     = (const float*)d_in[8];
    const float* bo     = (const float*)d_in[9];
    const float* W1     = (const float*)d_in[10];
    const float* b1     = (const float*)d_in[11];
    const float* W2     = (const float*)d_in[12];
    const float* b2     = (const float*)d_in[13];
    const float* Wc     = (const float*)d_in[14];
    const float* bc     = (const float*)d_in[15];
    const float* Wd     = (const float*)d_in[16];
    const float* bd     = (const float*)d_in[17];
    float* outp = (float*)d_out;
    (void)in_sizes; (void)n_in; (void)out_size;

    float *p_out, *p_mh;
    bf16 *p_outb, *p_qb, *p_kb, *p_vtb, *p_catb, *p_ffb, *p_wtb;
    cudaGetSymbolAddress((void**)&p_out,  g_out);
    cudaGetSymbolAddress((void**)&p_mh,   g_mh);
    cudaGetSymbolAddress((void**)&p_outb, g_outb);
    cudaGetSymbolAddress((void**)&p_qb,   g_qb);
    cudaGetSymbolAddress((void**)&p_kb,   g_kb);
    cudaGetSymbolAddress((void**)&p_vtb,  g_vtb);
    cudaGetSymbolAddress((void**)&p_catb, g_catb);
    cudaGetSymbolAddress((void**)&p_ffb,  g_ffb);
    cudaGetSymbolAddress((void**)&p_wtb,  g_wtb);

    cudaFuncSetAttribute(gemmB<0,8>,  cudaFuncAttributeMaxDynamicSharedMemorySize, SMEM_G);
    cudaFuncSetAttribute(gemmB<1,8>,  cudaFuncAttributeMaxDynamicSharedMemorySize, SMEM_G);
    cudaFuncSetAttribute(gemmB<2,8>,  cudaFuncAttributeMaxDynamicSharedMemorySize, SMEM_G);
    cudaFuncSetAttribute(gemmB<4,8>,  cudaFuncAttributeMaxDynamicSharedMemorySize, SMEM_G);
    cudaFuncSetAttribute(gemmB<5,16>, cudaFuncAttributeMaxDynamicSharedMemorySize, SMEM_G);
    cudaFuncSetAttribute(flashB,      cudaFuncAttributeMaxDynamicSharedMemorySize, FL_SMEM);

    const float scale = 0.044194173824159216f;  // 1/sqrt(512)
    dim3 tthr(32, 8);

    // ---- pre-transpose+convert all weights to bf16 [N,K] ----
    for (int i = 0; i < L_; i++) {
        bf16* wt = p_wtb + (size_t)i * LWT_;
        transpose_kernel<<<dim3(2, 16, 8), tthr>>>(Wq + (size_t)i*H_*E_*D_, wt + QT_,  512, 64);
        transpose_kernel<<<dim3(2, 16, 8), tthr>>>(Wk + (size_t)i*H_*E_*D_, wt + KT_,  512, 64);
        transpose_kernel<<<dim3(2, 16, 8), tthr>>>(Wv + (size_t)i*H_*E_*D_, wt + VTW_, 512, 64);
        transpose_kernel<<<dim3(16, 16, 1), tthr>>>(Wo + (size_t)i*E_*E_,   wt + OT_,  512, 512);
        transpose_kernel<<<dim3(32, 16, 1), tthr>>>(W1 + (size_t)i*E_*2*E_, wt + W1T_, 512, 1024);
        transpose_kernel<<<dim3(16, 32, 1), tthr>>>(W2 + (size_t)i*2*E_*E_, wt + W2T_, 1024, 512);
    }

    embed_kernel<<<(M_ * E_) / 1024, 256>>>(tokens, emb);

    for (int i = 0; i < L_; i++) {
        bf16* wt = p_wtb + (size_t)i * LWT_;
        GB a;

        // Q = out @ Wq^T + bq  -> bf16 [B,S,H*D]
        a = { p_outb, wt + QT_, bq + (size_t)i*512, nullptr, nullptr, p_qb, 512, 512, 512 };
        gemmB<0,8><<<dim3(4, 256), 256, SMEM_G>>>(a);
        // K
        a = { p_outb, wt + KT_, bk + (size_t)i*512, nullptr, nullptr, p_kb, 512, 512, 512 };
        gemmB<0,8><<<dim3(4, 256), 256, SMEM_G>>>(a);
        // V^T = Wv^T @ out^T + bv  -> bf16 [B,H,D,S]  (A=weights, B=activations)
        a = { wt + VTW_, p_outb, bv + (size_t)i*512, nullptr, nullptr, p_vtb, 512, 512, 0 };
        gemmB<1,8><<<dim3(256, 4), 256, SMEM_G>>>(a);

        // fused attention -> g_catb (bf16)
        flashB<<<dim3(S_/128, BH_), 256, FL_SMEM>>>(scale);

        // mh = cat @ Wo^T + bo  -> fp32
        a = { p_catb, wt + OT_, bo + (size_t)i*512, nullptr, p_mh, nullptr, 512, 512, 512 };
        gemmB<2,8><<<dim3(4, 256), 256, SMEM_G>>>(a);

        addnorm_kernel<<<M_, 128>>>();

        // ff = relu(out @ W1^T + b1)  -> bf16
        a = { p_outb, wt + W1T_, b1 + (size_t)i*1024, nullptr, nullptr, p_ffb, 512, 512, 1024 };
        gemmB<4,8><<<dim3(8, 256), 256, SMEM_G>>>(a);

        // out = ff @ W2^T + b2 + out  -> fp32 + bf16
        a = { p_ffb, wt + W2T_, b2 + (size_t)i*512, p_out, p_out, p_outb, 1024, 1024, 512 };
        gemmB<5,16><<<dim3(4, 256), 256, SMEM_G>>>(a);
    }

    conv_kernel<<<B_ * LOUT_, 256>>>(Wc, bc);
    dense_softmax_kernel<<<B_, 256>>>(Wd, bd, outp);
}